// round 10
// baseline (speedup 1.0000x reference)
#include <cuda_runtime.h>
#include <cuda_bf16.h>
#include <cstdint>

#define NN   100000
#define EE   1600000
#define IND  128
#define HIDD 256
#define OUTD 64
#define NB_SCAN 196   // ceil(NN/512)

// ---------------- scratch (device globals: allocation-free rule) -------------
__device__ int   g_eidx[EE];
__device__ int   g_count[NN];
__device__ int   g_cursor[NN];
__device__ int   g_bsum[NB_SCAN];
__device__ int   g_off[NN + 1];
__device__ float g_inv[NN];
__device__ float g_pq[NN * (2 * OUTD)];
__device__ int   g_is64;

// pre-split bf16 operands (hi/lo error-compensation pairs)
__device__ __align__(16) __nv_bfloat16 g_a1h[NN * 256];   // [mean|x] hi
__device__ __align__(16) __nv_bfloat16 g_a1l[NN * 256];   // [mean|x] lo
__device__ __align__(16) __nv_bfloat16 g_hh[NN * 256];    // h hi
__device__ __align__(16) __nv_bfloat16 g_hl[NN * 256];    // h lo
__device__ __align__(16) __nv_bfloat16 g_w1h[256 * 256];
__device__ __align__(16) __nv_bfloat16 g_w1l[256 * 256];
__device__ __align__(16) __nv_bfloat16 g_w2h[128 * 256];
__device__ __align__(16) __nv_bfloat16 g_w2l[128 * 256];

// ---------------- helpers -----------------------------------------------------
__device__ __forceinline__ uint32_t smem_u32(const void* p) {
    uint32_t a;
    asm("{ .reg .u64 t; cvta.to.shared.u64 t, %1; cvt.u32.u64 %0, t; }"
        : "=r"(a) : "l"(p));
    return a;
}
__device__ __forceinline__ void ldsm4(uint32_t* r, uint32_t addr) {
    asm volatile("ldmatrix.sync.aligned.m8n8.x4.shared.b16 {%0,%1,%2,%3}, [%4];"
                 : "=r"(r[0]), "=r"(r[1]), "=r"(r[2]), "=r"(r[3]) : "r"(addr));
}
__device__ __forceinline__ void mma_bf16(float* d, const uint32_t* a,
                                         uint32_t b0, uint32_t b1) {
    asm volatile(
        "mma.sync.aligned.m16n8k16.row.col.f32.bf16.bf16.f32 "
        "{%0,%1,%2,%3}, {%4,%5,%6,%7}, {%8,%9}, {%0,%1,%2,%3};"
        : "+f"(d[0]), "+f"(d[1]), "+f"(d[2]), "+f"(d[3])
        : "r"(a[0]), "r"(a[1]), "r"(a[2]), "r"(a[3]), "r"(b0), "r"(b1));
}
__device__ __forceinline__ void bsplit(float v, __nv_bfloat16& h, __nv_bfloat16& l) {
    h = __float2bfloat16(v);
    l = __float2bfloat16(v - __bfloat162float(h));
}
__device__ __forceinline__ void cpasync16(uint32_t dst, const void* src, int srcsz) {
    asm volatile("cp.async.cg.shared.global [%0], [%1], 16, %2;"
                 :: "r"(dst), "l"(src), "r"(srcsz));
}
__device__ __forceinline__ void cp_commit() {
    asm volatile("cp.async.commit_group;");
}
__device__ __forceinline__ void cp_wait2() {
    asm volatile("cp.async.wait_group 2;");
}
// edge-index readers (dtype-branched; g_is64 is uniform)
__device__ __forceinline__ int ld_src(const void* ei, int t) {
    return g_is64 ? (int)((const long long*)ei)[t] : ((const int*)ei)[t];
}
__device__ __forceinline__ int ld_dst(const void* ei, int t) {
    return g_is64 ? (int)((const long long*)ei)[EE + t] : ((const int*)ei)[EE + t];
}

// ---------------- index dtype detection + zero counters ------------------------
__global__ void k_detect(const void* __restrict__ ei) {
    __shared__ int s_any;
    if (threadIdx.x == 0) s_any = 0;
    __syncthreads();
    const uint2* p = (const uint2*)ei;
    unsigned any = 0;
    for (int i = threadIdx.x; i < 2048; i += blockDim.x) any |= p[i].y;
    if (any) atomicOr(&s_any, 1);
    __syncthreads();
    if (threadIdx.x == 0) g_is64 = (s_any == 0) ? 1 : 0;
}

__global__ void k_zero_cnt() {
    int t = blockIdx.x * blockDim.x + threadIdx.x;
    if (t < NN) { g_count[t] = 0; g_cursor[t] = 0; }
}

// histogram of dst straight from edge_index
__global__ void k_hist(const void* __restrict__ ei) {
    int t = blockIdx.x * blockDim.x + threadIdx.x;
    if (t >= EE) return;
    atomicAdd(&g_count[ld_dst(ei, t)], 1);
}

// ---------------- exclusive scan of g_count -> g_off --------------------------
__global__ void k_s1() {
    int t = blockIdx.x * 512 + threadIdx.x;
    int v = (t < NN) ? g_count[t] : 0;
    __shared__ int sw[16];
    int wid = threadIdx.x >> 5, lid = threadIdx.x & 31;
    int s = v;
#pragma unroll
    for (int o = 16; o > 0; o >>= 1) s += __shfl_down_sync(0xffffffff, s, o);
    if (lid == 0) sw[wid] = s;
    __syncthreads();
    if (wid == 0) {
        int x = (lid < 16) ? sw[lid] : 0;
#pragma unroll
        for (int o = 16; o > 0; o >>= 1) x += __shfl_down_sync(0xffffffff, x, o);
        if (lid == 0) g_bsum[blockIdx.x] = x;
    }
}
__global__ void k_s2() {
    if (threadIdx.x == 0) {
        int run = 0;
        for (int i = 0; i < NB_SCAN; i++) { int v = g_bsum[i]; g_bsum[i] = run; run += v; }
        g_off[NN] = run;
    }
}
__global__ void k_s3() {
    __shared__ int sm[512];
    int t = blockIdx.x * 512 + threadIdx.x;
    int v = (t < NN) ? g_count[t] : 0;
    sm[threadIdx.x] = v;
    __syncthreads();
#pragma unroll
    for (int o = 1; o < 512; o <<= 1) {
        int tmp = (threadIdx.x >= o) ? sm[threadIdx.x - o] : 0;
        __syncthreads();
        sm[threadIdx.x] += tmp;
        __syncthreads();
    }
    if (t < NN) g_off[t] = sm[threadIdx.x] - v + g_bsum[blockIdx.x];
}

// bucket-scatter src ids by dst, straight from edge_index
__global__ void k_build(const void* __restrict__ ei) {
    int t = blockIdx.x * blockDim.x + threadIdx.x;
    if (t >= EE) return;
    int d = ld_dst(ei, t);
    int s = ld_src(ei, t);
    int p = g_off[d] + atomicAdd(&g_cursor[d], 1);
    g_eidx[p] = s;
}

// ---------------- weight split (runs once, tiny) -------------------------------
__global__ void k_splitw(const float* __restrict__ W1l, const float* __restrict__ W1r,
                         const float* __restrict__ W2l, const float* __restrict__ W2r) {
    int t = blockIdx.x * blockDim.x + threadIdx.x;
    if (t < 256 * 256) {
        int row = t >> 8, k = t & 255;
        float v = (k < 128) ? W1l[row * 128 + k] : W1r[row * 128 + (k - 128)];
        bsplit(v, g_w1h[t], g_w1l[t]);
    } else if (t < 256 * 256 + 128 * 256) {
        int u = t - 256 * 256;
        int row = u >> 8, k = u & 255;
        float v = (row < 64) ? W2l[row * 256 + k] : W2r[(row - 64) * 256 + k];
        bsplit(v, g_w2h[u], g_w2l[u]);
    }
}

// ---------------- layer-1 segmented mean + split: warp per node ----------------
__global__ void k_reduce1(const float* __restrict__ x) {
    int wgl = (blockIdx.x * blockDim.x + threadIdx.x) >> 5;
    int lane = threadIdx.x & 31;
    if (wgl >= NN) return;
    int beg = g_off[wgl], end = g_off[wgl + 1];
    float4 acc = make_float4(0.f, 0.f, 0.f, 0.f);
    for (int base = beg; base < end; base += 32) {
        int rem = end - base;
        int eid = (lane < rem) ? g_eidx[base + lane] : 0;
        int cnt = rem < 32 ? rem : 32;
#pragma unroll 4
        for (int j = 0; j < cnt; j++) {
            int s = __shfl_sync(0xffffffff, eid, j);
            float4 v = ((const float4*)x)[s * 32 + lane];
            acc.x += v.x; acc.y += v.y; acc.z += v.z; acc.w += v.w;
        }
    }
    float inv = 1.0f / fmaxf((float)(end - beg), 1.0f);
    acc.x *= inv; acc.y *= inv; acc.z *= inv; acc.w *= inv;
    if (lane == 0) g_inv[wgl] = inv;

    __nv_bfloat16 h[4], l[4];
    bsplit(acc.x, h[0], l[0]); bsplit(acc.y, h[1], l[1]);
    bsplit(acc.z, h[2], l[2]); bsplit(acc.w, h[3], l[3]);
    *(ushort4*)(g_a1h + wgl * 256 + lane * 4) = *(ushort4*)h;
    *(ushort4*)(g_a1l + wgl * 256 + lane * 4) = *(ushort4*)l;
    float4 xv = ((const float4*)x)[wgl * 32 + lane];
    bsplit(xv.x, h[0], l[0]); bsplit(xv.y, h[1], l[1]);
    bsplit(xv.z, h[2], l[2]); bsplit(xv.w, h[3], l[3]);
    *(ushort4*)(g_a1h + wgl * 256 + 128 + lane * 4) = *(ushort4*)h;
    *(ushort4*)(g_a1l + wgl * 256 + 128 + lane * 4) = *(ushort4*)l;
}

// ======================= 3-stage pipelined mma.sync GEMM =====================
// MODE 0: h = relu(A1 @ W1^T + b1)   N=256 (grid.y=2)
// MODE 1: pq = H @ W2^T              N=128 (grid.y=1)
// BK=32, triple-buffered cp.async. Stage = {AH,AL,BH,BL} x 8KB = 32KB.
#define STG   32768
#define OP_AH 0
#define OP_AL 8192
#define OP_BH 16384
#define OP_BL 24576

template <int MODE>
__global__ __launch_bounds__(256) void k_gemm_mma(const float* __restrict__ bias)
{
    extern __shared__ char smem[];
    const uint32_t sb = smem_u32(smem);

    const int tid  = threadIdx.x;
    const int wid  = tid >> 5;
    const int lane = tid & 31;
    const int wm   = wid & 3;
    const int wn   = wid >> 2;
    const int m0   = blockIdx.x * 128;
    const int j0   = blockIdx.y * 128;

    const __nv_bfloat16* Ah = (MODE == 0) ? g_a1h : g_hh;
    const __nv_bfloat16* Al = (MODE == 0) ? g_a1l : g_hl;
    const __nv_bfloat16* Bh = (MODE == 0) ? g_w1h : g_w2h;
    const __nv_bfloat16* Bl = (MODE == 0) ? g_w1l : g_w2l;

    float acc[2][8][4];
#pragma unroll
    for (int a = 0; a < 2; a++)
#pragma unroll
        for (int b = 0; b < 8; b++)
#pragma unroll
            for (int c = 0; c < 4; c++) acc[a][b][c] = 0.f;

    const int r8   = lane & 7;
    const int subm = lane >> 3;

    auto load_chunk = [&](int ch, int s) {
        const int kt = ch * 32;
        const uint32_t sbase = sb + s * STG;
#pragma unroll
        for (int i = 0; i < 2; i++) {
            int idx = tid + i * 256;            // 0..511
            int row = idx >> 2;                 // 0..127
            int c   = idx & 3;                  // 16B chunk along k
            uint32_t off = (uint32_t)(row * 64 + ((c ^ ((row >> 1) & 3)) * 16));
            int gr = m0 + row;
            int szA = (gr < NN) ? 16 : 0;
            const __nv_bfloat16* pa = Ah + (size_t)gr * 256 + kt + c * 8;
            const __nv_bfloat16* pl = Al + (size_t)gr * 256 + kt + c * 8;
            if (gr >= NN) { pa = Ah; pl = Al; }   // safe address, zfilled
            cpasync16(sbase + OP_AH + off, pa, szA);
            cpasync16(sbase + OP_AL + off, pl, szA);
            cpasync16(sbase + OP_BH + off, Bh + (size_t)(j0 + row) * 256 + kt + c * 8, 16);
            cpasync16(sbase + OP_BL + off, Bl + (size_t)(j0 + row) * 256 + kt + c * 8, 16);
        }
    };

    load_chunk(0, 0);
    cp_commit();
    load_chunk(1, 1);
    cp_commit();

    for (int ch = 0; ch < 8; ch++) {
        if (ch < 6) load_chunk(ch + 2, (ch + 2) % 3);
        cp_commit();                  // (empty group on tail iters)
        cp_wait2();                   // chunk ch's group resident
        __syncthreads();

        const uint32_t sbase = sb + (ch % 3) * STG;
#pragma unroll
        for (int ks = 0; ks < 2; ks++) {
            const int cb = ks * 2;
            uint32_t ahf[2][4], alf[2][4];
#pragma unroll
            for (int tm = 0; tm < 2; tm++) {
                int arow = wm * 32 + tm * 16 + (subm & 1) * 8 + r8;
                int achk = cb + (subm >> 1);
                uint32_t ab = (uint32_t)(arow * 64 + ((achk ^ ((arow >> 1) & 3)) * 16));
                ldsm4(ahf[tm], sbase + OP_AH + ab);
                ldsm4(alf[tm], sbase + OP_AL + ab);
            }
            uint32_t bh[16], bl[16];
#pragma unroll
            for (int g = 0; g < 4; g++) {
                int brow = wn * 64 + g * 16 + (subm >> 1) * 8 + r8;
                int bchk = cb + (subm & 1);
                uint32_t bb = (uint32_t)(brow * 64 + ((bchk ^ ((brow >> 1) & 3)) * 16));
                ldsm4(&bh[g * 4], sbase + OP_BH + bb);
                ldsm4(&bl[g * 4], sbase + OP_BL + bb);
            }
#pragma unroll
            for (int tm = 0; tm < 2; tm++)
#pragma unroll
                for (int tn = 0; tn < 8; tn++) {
                    mma_bf16(acc[tm][tn], ahf[tm], bh[tn * 2], bh[tn * 2 + 1]);
                    mma_bf16(acc[tm][tn], ahf[tm], bl[tn * 2], bl[tn * 2 + 1]);
                    mma_bf16(acc[tm][tn], alf[tm], bh[tn * 2], bh[tn * 2 + 1]);
                }
        }
        __syncthreads();   // stage (ch%3) fully consumed before iter ch+1 refills it
    }

    // ---- epilogue: MODE0 writes split h; MODE1 writes fp32 pq -----------------
    const int qrow = lane >> 2;
    const int qcol = (lane & 3) * 2;
#pragma unroll
    for (int tm = 0; tm < 2; tm++) {
#pragma unroll
        for (int half = 0; half < 2; half++) {
            int gr = m0 + wm * 32 + tm * 16 + half * 8 + qrow;
            if (gr >= NN) continue;
#pragma unroll
            for (int tn = 0; tn < 8; tn++) {
                int gc = j0 + wn * 64 + tn * 8 + qcol;
                float v0 = acc[tm][tn][half * 2 + 0];
                float v1 = acc[tm][tn][half * 2 + 1];
                if (MODE == 0) {
                    v0 = fmaxf(v0 + bias[gc], 0.f);
                    v1 = fmaxf(v1 + bias[gc + 1], 0.f);
                    __nv_bfloat16 h0, l0, h1, l1;
                    bsplit(v0, h0, l0);
                    bsplit(v1, h1, l1);
                    __nv_bfloat16 hp[2] = {h0, h1}, lp[2] = {l0, l1};
                    *(uint32_t*)(g_hh + gr * 256 + gc) = *(uint32_t*)hp;
                    *(uint32_t*)(g_hl + gr * 256 + gc) = *(uint32_t*)lp;
                } else {
                    *(float2*)(g_pq + gr * (2 * OUTD) + gc) = make_float2(v0, v1);
                }
            }
        }
    }
}

// ---------------- layer-2 segmented mean + epilogue: warp per node ------------
__global__ void k_reduce2(const float* __restrict__ b2, float* __restrict__ out) {
    int wgl = (blockIdx.x * blockDim.x + threadIdx.x) >> 5;
    int lane = threadIdx.x & 31;
    if (wgl >= NN) return;
    int beg = g_off[wgl], end = g_off[wgl + 1];
    float2 acc = make_float2(0.f, 0.f);
    for (int base = beg; base < end; base += 32) {
        int rem = end - base;
        int eid = (lane < rem) ? g_eidx[base + lane] : 0;
        int cnt = rem < 32 ? rem : 32;
#pragma unroll 4
        for (int j = 0; j < cnt; j++) {
            int s = __shfl_sync(0xffffffff, eid, j);
            float2 v = ((const float2*)g_pq)[s * 64 + lane];
            acc.x += v.x; acc.y += v.y;
        }
    }
    float inv = g_inv[wgl];
    float2 q  = ((const float2*)g_pq)[wgl * 64 + 32 + lane];
    float2 bb = ((const float2*)b2)[lane];
    float2 r;
    r.x = fmaf(acc.x, inv, bb.x) + q.x;
    r.y = fmaf(acc.y, inv, bb.y) + q.y;
    ((float2*)out)[wgl * 32 + lane] = r;
}

// ---------------- launch ------------------------------------------------------
extern "C" void kernel_launch(void* const* d_in, const int* in_sizes, int n_in,
                              void* d_out, int out_size) {
    const float* x   = (const float*)d_in[0];
    const void*  ei  = d_in[1];
    const float* W1l = (const float*)d_in[2];
    const float* b1  = (const float*)d_in[3];
    const float* W1r = (const float*)d_in[4];
    const float* W2l = (const float*)d_in[5];
    const float* b2  = (const float*)d_in[6];
    const float* W2r = (const float*)d_in[7];
    float* out = (float*)d_out;

    const int SMEM = 3 * STG;   // 98304
    cudaFuncSetAttribute(k_gemm_mma<0>,
                         cudaFuncAttributeMaxDynamicSharedMemorySize, SMEM);
    cudaFuncSetAttribute(k_gemm_mma<1>,
                         cudaFuncAttributeMaxDynamicSharedMemorySize, SMEM);

    k_detect<<<1, 256>>>(ei);
    k_zero_cnt<<<(NN + 255) / 256, 256>>>();
    k_hist<<<(EE + 255) / 256, 256>>>(ei);
    k_splitw<<<(256 * 256 + 128 * 256 + 255) / 256, 256>>>(W1l, W1r, W2l, W2r);

    k_s1<<<NB_SCAN, 512>>>();
    k_s2<<<1, 32>>>();
    k_s3<<<NB_SCAN, 512>>>();
    k_build<<<(EE + 255) / 256, 256>>>(ei);

    k_reduce1<<<(NN * 32 + 255) / 256, 256>>>(x);

    const int MT = (NN + 127) / 128;   // 782
    k_gemm_mma<0><<<dim3(MT, 2), 256, SMEM>>>(b1);
    k_gemm_mma<1><<<dim3(MT, 1), 256, SMEM>>>(b1);

    k_reduce2<<<(NN * 32 + 255) / 256, 256>>>(b2, out);
}

// round 11
// speedup vs baseline: 1.0555x; 1.0555x over previous
#include <cuda_runtime.h>
#include <cuda_fp16.h>
#include <cstdint>

#define NN   100000
#define EE   1600000
#define IND  128
#define HIDD 256
#define OUTD 64
#define NB_SCAN 196   // ceil(NN/512)

// ---------------- scratch (device globals: allocation-free rule) -------------
__device__ int   g_src[EE];
__device__ int   g_dst[EE];
__device__ int   g_eidx[EE];
__device__ int   g_count[NN];
__device__ int   g_cursor[NN];
__device__ int   g_bsum[NB_SCAN];
__device__ int   g_off[NN + 1];
__device__ float g_inv[NN];
__device__ float g_pq[NN * (2 * OUTD)];
__device__ int   g_is64;

// fp16 operands: activations split hi/lo, weights single fp16
__device__ __align__(16) __half g_a1h[NN * 256];   // [mean|x] hi
__device__ __align__(16) __half g_a1l[NN * 256];   // [mean|x] lo
__device__ __align__(16) __half g_hh[NN * 256];    // h hi
__device__ __align__(16) __half g_hl[NN * 256];    // h lo
__device__ __align__(16) __half g_w1[256 * 256];
__device__ __align__(16) __half g_w2[128 * 256];

// ---------------- helpers -----------------------------------------------------
__device__ __forceinline__ uint32_t smem_u32(const void* p) {
    uint32_t a;
    asm("{ .reg .u64 t; cvta.to.shared.u64 t, %1; cvt.u32.u64 %0, t; }"
        : "=r"(a) : "l"(p));
    return a;
}
__device__ __forceinline__ void ldsm4(uint32_t* r, uint32_t addr) {
    asm volatile("ldmatrix.sync.aligned.m8n8.x4.shared.b16 {%0,%1,%2,%3}, [%4];"
                 : "=r"(r[0]), "=r"(r[1]), "=r"(r[2]), "=r"(r[3]) : "r"(addr));
}
__device__ __forceinline__ void mma_f16(float* d, const uint32_t* a,
                                        uint32_t b0, uint32_t b1) {
    asm volatile(
        "mma.sync.aligned.m16n8k16.row.col.f32.f16.f16.f32 "
        "{%0,%1,%2,%3}, {%4,%5,%6,%7}, {%8,%9}, {%0,%1,%2,%3};"
        : "+f"(d[0]), "+f"(d[1]), "+f"(d[2]), "+f"(d[3])
        : "r"(a[0]), "r"(a[1]), "r"(a[2]), "r"(a[3]), "r"(b0), "r"(b1));
}
__device__ __forceinline__ void hsplit(float v, __half& h, __half& l) {
    h = __float2half_rn(v);
    l = __float2half_rn(v - __half2float(h));
}
__device__ __forceinline__ void cpasync16(uint32_t dst, const void* src, int srcsz) {
    asm volatile("cp.async.cg.shared.global [%0], [%1], 16, %2;"
                 :: "r"(dst), "l"(src), "r"(srcsz));
}
__device__ __forceinline__ void cp_commit() {
    asm volatile("cp.async.commit_group;");
}
__device__ __forceinline__ void cp_wait1() {
    asm volatile("cp.async.wait_group 1;");
}

// ---------------- index dtype detection ---------------------------------------
__global__ void k_detect(const void* __restrict__ ei) {
    __shared__ int s_any;
    if (threadIdx.x == 0) s_any = 0;
    __syncthreads();
    const uint2* p = (const uint2*)ei;
    unsigned any = 0;
    for (int i = threadIdx.x; i < 2048; i += blockDim.x) any |= p[i].y;
    if (any) atomicOr(&s_any, 1);
    __syncthreads();
    if (threadIdx.x == 0) g_is64 = (s_any == 0) ? 1 : 0;
}

__global__ void k_zero_cnt() {
    int t = blockIdx.x * blockDim.x + threadIdx.x;
    if (t < NN) { g_count[t] = 0; g_cursor[t] = 0; }
}

__global__ void k_convert(const void* __restrict__ ei) {
    int t = blockIdx.x * blockDim.x + threadIdx.x;
    if (t >= 2 * EE) return;
    int v;
    if (g_is64) v = (int)((const long long*)ei)[t];
    else        v = ((const int*)ei)[t];
    if (t < EE) g_src[t] = v;
    else { g_dst[t - EE] = v; atomicAdd(&g_count[v], 1); }
}

// ---------------- exclusive scan of g_count -> g_off --------------------------
__global__ void k_s1() {
    int t = blockIdx.x * 512 + threadIdx.x;
    int v = (t < NN) ? g_count[t] : 0;
    __shared__ int sw[16];
    int wid = threadIdx.x >> 5, lid = threadIdx.x & 31;
    int s = v;
#pragma unroll
    for (int o = 16; o > 0; o >>= 1) s += __shfl_down_sync(0xffffffff, s, o);
    if (lid == 0) sw[wid] = s;
    __syncthreads();
    if (wid == 0) {
        int x = (lid < 16) ? sw[lid] : 0;
#pragma unroll
        for (int o = 16; o > 0; o >>= 1) x += __shfl_down_sync(0xffffffff, x, o);
        if (lid == 0) g_bsum[blockIdx.x] = x;
    }
}
__global__ void k_s2() {
    if (threadIdx.x == 0) {
        int run = 0;
        for (int i = 0; i < NB_SCAN; i++) { int v = g_bsum[i]; g_bsum[i] = run; run += v; }
        g_off[NN] = run;
    }
}
__global__ void k_s3() {
    __shared__ int sm[512];
    int t = blockIdx.x * 512 + threadIdx.x;
    int v = (t < NN) ? g_count[t] : 0;
    sm[threadIdx.x] = v;
    __syncthreads();
#pragma unroll
    for (int o = 1; o < 512; o <<= 1) {
        int tmp = (threadIdx.x >= o) ? sm[threadIdx.x - o] : 0;
        __syncthreads();
        sm[threadIdx.x] += tmp;
        __syncthreads();
    }
    if (t < NN) g_off[t] = sm[threadIdx.x] - v + g_bsum[blockIdx.x];
}

__global__ void k_build() {
    int t = blockIdx.x * blockDim.x + threadIdx.x;
    if (t >= EE) return;
    int d = g_dst[t];
    int p = g_off[d] + atomicAdd(&g_cursor[d], 1);
    g_eidx[p] = g_src[t];
}

// ---------------- weight convert (runs once, tiny) -----------------------------
__global__ void k_splitw(const float* __restrict__ W1l, const float* __restrict__ W1r,
                         const float* __restrict__ W2l, const float* __restrict__ W2r) {
    int t = blockIdx.x * blockDim.x + threadIdx.x;
    if (t < 256 * 256) {
        int row = t >> 8, k = t & 255;
        float v = (k < 128) ? W1l[row * 128 + k] : W1r[row * 128 + (k - 128)];
        g_w1[t] = __float2half_rn(v);
    } else if (t < 256 * 256 + 128 * 256) {
        int u = t - 256 * 256;
        int row = u >> 8, k = u & 255;
        float v = (row < 64) ? W2l[row * 256 + k] : W2r[(row - 64) * 256 + k];
        g_w2[u] = __float2half_rn(v);
    }
}

// ---------------- layer-1 segmented mean + split: warp per node ----------------
__global__ void k_reduce1(const float* __restrict__ x) {
    int wgl = (blockIdx.x * blockDim.x + threadIdx.x) >> 5;
    int lane = threadIdx.x & 31;
    if (wgl >= NN) return;
    int beg = g_off[wgl], end = g_off[wgl + 1];
    float4 acc = make_float4(0.f, 0.f, 0.f, 0.f);
    for (int base = beg; base < end; base += 32) {
        int rem = end - base;
        int eid = (lane < rem) ? g_eidx[base + lane] : 0;
        int cnt = rem < 32 ? rem : 32;
#pragma unroll 4
        for (int j = 0; j < cnt; j++) {
            int s = __shfl_sync(0xffffffff, eid, j);
            float4 v = ((const float4*)x)[s * 32 + lane];
            acc.x += v.x; acc.y += v.y; acc.z += v.z; acc.w += v.w;
        }
    }
    float inv = 1.0f / fmaxf((float)(end - beg), 1.0f);
    acc.x *= inv; acc.y *= inv; acc.z *= inv; acc.w *= inv;
    if (lane == 0) g_inv[wgl] = inv;

    __half h[4], l[4];
    hsplit(acc.x, h[0], l[0]); hsplit(acc.y, h[1], l[1]);
    hsplit(acc.z, h[2], l[2]); hsplit(acc.w, h[3], l[3]);
    *(ushort4*)(g_a1h + wgl * 256 + lane * 4) = *(ushort4*)h;
    *(ushort4*)(g_a1l + wgl * 256 + lane * 4) = *(ushort4*)l;
    float4 xv = ((const float4*)x)[wgl * 32 + lane];
    hsplit(xv.x, h[0], l[0]); hsplit(xv.y, h[1], l[1]);
    hsplit(xv.z, h[2], l[2]); hsplit(xv.w, h[3], l[3]);
    *(ushort4*)(g_a1h + wgl * 256 + 128 + lane * 4) = *(ushort4*)h;
    *(ushort4*)(g_a1l + wgl * 256 + 128 + lane * 4) = *(ushort4*)l;
}

// ======================= pipelined fp16 2-term mma.sync GEMM =================
// MODE 0: h = relu(A1 @ W1^T + b1)   N=256 (grid.y=2)
// MODE 1: pq = H @ W2^T              N=128 (grid.y=1)
// D += Ah*B + Al*B  (A = Ah+Al exact to 2^-22; B single fp16, err ~2^-11)
// BK=32, double-buffered cp.async. Stage = {AH,AL,BH} x 8KB = 24KB.
#define STG   24576
#define OP_AH 0
#define OP_AL 8192
#define OP_BH 16384

template <int MODE>
__global__ __launch_bounds__(256) void k_gemm_mma(const float* __restrict__ bias)
{
    extern __shared__ char smem[];
    const uint32_t sb = smem_u32(smem);

    const int tid  = threadIdx.x;
    const int wid  = tid >> 5;
    const int lane = tid & 31;
    const int wm   = wid & 3;
    const int wn   = wid >> 2;
    const int m0   = blockIdx.x * 128;
    const int j0   = blockIdx.y * 128;

    const __half* Ah = (MODE == 0) ? g_a1h : g_hh;
    const __half* Al = (MODE == 0) ? g_a1l : g_hl;
    const __half* Bh = (MODE == 0) ? g_w1 : g_w2;

    float acc[2][8][4];
#pragma unroll
    for (int a = 0; a < 2; a++)
#pragma unroll
        for (int b = 0; b < 8; b++)
#pragma unroll
            for (int c = 0; c < 4; c++) acc[a][b][c] = 0.f;

    const int r8   = lane & 7;
    const int subm = lane >> 3;

    auto load_chunk = [&](int ch, int s) {
        const int kt = ch * 32;
        const uint32_t sbase = sb + s * STG;
#pragma unroll
        for (int i = 0; i < 2; i++) {
            int idx = tid + i * 256;            // 0..511
            int row = idx >> 2;                 // 0..127
            int c   = idx & 3;                  // 16B chunk along k
            uint32_t off = (uint32_t)(row * 64 + ((c ^ ((row >> 1) & 3)) * 16));
            int gr = m0 + row;
            int szA = (gr < NN) ? 16 : 0;
            const __half* pa = Ah + (size_t)gr * 256 + kt + c * 8;
            const __half* pl = Al + (size_t)gr * 256 + kt + c * 8;
            if (gr >= NN) { pa = Ah; pl = Al; }   // safe address, zfilled
            cpasync16(sbase + OP_AH + off, pa, szA);
            cpasync16(sbase + OP_AL + off, pl, szA);
            cpasync16(sbase + OP_BH + off, Bh + (size_t)(j0 + row) * 256 + kt + c * 8, 16);
        }
    };

    load_chunk(0, 0);
    cp_commit();

    for (int ch = 0; ch < 8; ch++) {
        if (ch < 7) load_chunk(ch + 1, (ch + 1) & 1);
        cp_commit();                  // (empty group on last iter)
        cp_wait1();                   // chunk ch resident
        __syncthreads();

        const uint32_t sbase = sb + (ch & 1) * STG;
#pragma unroll
        for (int ks = 0; ks < 2; ks++) {
            const int cb = ks * 2;
            uint32_t ahf[2][4], alf[2][4];
#pragma unroll
            for (int tm = 0; tm < 2; tm++) {
                int arow = wm * 32 + tm * 16 + (subm & 1) * 8 + r8;
                int achk = cb + (subm >> 1);
                uint32_t ab = (uint32_t)(arow * 64 + ((achk ^ ((arow >> 1) & 3)) * 16));
                ldsm4(ahf[tm], sbase + OP_AH + ab);
                ldsm4(alf[tm], sbase + OP_AL + ab);
            }
            uint32_t bh[16];
#pragma unroll
            for (int g = 0; g < 4; g++) {
                int brow = wn * 64 + g * 16 + (subm >> 1) * 8 + r8;
                int bchk = cb + (subm & 1);
                uint32_t bb = (uint32_t)(brow * 64 + ((bchk ^ ((brow >> 1) & 3)) * 16));
                ldsm4(&bh[g * 4], sbase + OP_BH + bb);
            }
#pragma unroll
            for (int tm = 0; tm < 2; tm++)
#pragma unroll
                for (int tn = 0; tn < 8; tn++) {
                    mma_f16(acc[tm][tn], ahf[tm], bh[tn * 2], bh[tn * 2 + 1]);
                    mma_f16(acc[tm][tn], alf[tm], bh[tn * 2], bh[tn * 2 + 1]);
                }
        }
        __syncthreads();
    }

    // ---- epilogue: MODE0 writes split h; MODE1 writes fp32 pq -----------------
    const int qrow = lane >> 2;
    const int qcol = (lane & 3) * 2;
#pragma unroll
    for (int tm = 0; tm < 2; tm++) {
#pragma unroll
        for (int half = 0; half < 2; half++) {
            int gr = m0 + wm * 32 + tm * 16 + half * 8 + qrow;
            if (gr >= NN) continue;
#pragma unroll
            for (int tn = 0; tn < 8; tn++) {
                int gc = j0 + wn * 64 + tn * 8 + qcol;
                float v0 = acc[tm][tn][half * 2 + 0];
                float v1 = acc[tm][tn][half * 2 + 1];
                if (MODE == 0) {
                    v0 = fmaxf(v0 + bias[gc], 0.f);
                    v1 = fmaxf(v1 + bias[gc + 1], 0.f);
                    __half h0, l0, h1, l1;
                    hsplit(v0, h0, l0);
                    hsplit(v1, h1, l1);
                    __half hp[2] = {h0, h1}, lp[2] = {l0, l1};
                    *(uint32_t*)(g_hh + gr * 256 + gc) = *(uint32_t*)hp;
                    *(uint32_t*)(g_hl + gr * 256 + gc) = *(uint32_t*)lp;
                } else {
                    *(float2*)(g_pq + gr * (2 * OUTD) + gc) = make_float2(v0, v1);
                }
            }
        }
    }
}

// ---------------- layer-2 segmented mean + epilogue: warp per node ------------
__global__ void k_reduce2(const float* __restrict__ b2, float* __restrict__ out) {
    int wgl = (blockIdx.x * blockDim.x + threadIdx.x) >> 5;
    int lane = threadIdx.x & 31;
    if (wgl >= NN) return;
    int beg = g_off[wgl], end = g_off[wgl + 1];
    float2 acc = make_float2(0.f, 0.f);
    for (int base = beg; base < end; base += 32) {
        int rem = end - base;
        int eid = (lane < rem) ? g_eidx[base + lane] : 0;
        int cnt = rem < 32 ? rem : 32;
#pragma unroll 4
        for (int j = 0; j < cnt; j++) {
            int s = __shfl_sync(0xffffffff, eid, j);
            float2 v = ((const float2*)g_pq)[s * 64 + lane];
            acc.x += v.x; acc.y += v.y;
        }
    }
    float inv = g_inv[wgl];
    float2 q  = ((const float2*)g_pq)[wgl * 64 + 32 + lane];
    float2 bb = ((const float2*)b2)[lane];
    float2 r;
    r.x = fmaf(acc.x, inv, bb.x) + q.x;
    r.y = fmaf(acc.y, inv, bb.y) + q.y;
    ((float2*)out)[wgl * 32 + lane] = r;
}

// ---------------- launch ------------------------------------------------------
extern "C" void kernel_launch(void* const* d_in, const int* in_sizes, int n_in,
                              void* d_out, int out_size) {
    const float* x   = (const float*)d_in[0];
    const void*  ei  = d_in[1];
    const float* W1l = (const float*)d_in[2];
    const float* b1  = (const float*)d_in[3];
    const float* W1r = (const float*)d_in[4];
    const float* W2l = (const float*)d_in[5];
    const float* b2  = (const float*)d_in[6];
    const float* W2r = (const float*)d_in[7];
    float* out = (float*)d_out;

    const int SMEM = 2 * STG;   // 49152
    cudaFuncSetAttribute(k_gemm_mma<0>,
                         cudaFuncAttributeMaxDynamicSharedMemorySize, SMEM);
    cudaFuncSetAttribute(k_gemm_mma<1>,
                         cudaFuncAttributeMaxDynamicSharedMemorySize, SMEM);

    k_detect<<<1, 256>>>(ei);
    k_zero_cnt<<<(NN + 255) / 256, 256>>>();
    k_convert<<<(2 * EE + 255) / 256, 256>>>(ei);
    k_splitw<<<(256 * 256 + 128 * 256 + 255) / 256, 256>>>(W1l, W1r, W2l, W2r);

    k_s1<<<NB_SCAN, 512>>>();
    k_s2<<<1, 32>>>();
    k_s3<<<NB_SCAN, 512>>>();
    k_build<<<(EE + 255) / 256, 256>>>();

    k_reduce1<<<(NN * 32 + 255) / 256, 256>>>(x);

    const int MT = (NN + 127) / 128;   // 782
    k_gemm_mma<0><<<dim3(MT, 2), 256, SMEM>>>(b1);
    k_gemm_mma<1><<<dim3(MT, 1), 256, SMEM>>>(b1);

    k_reduce2<<<(NN * 32 + 255) / 256, 256>>>(b2, out);
}

// round 12
// speedup vs baseline: 1.0781x; 1.0214x over previous
#include <cuda_runtime.h>
#include <cuda_fp16.h>
#include <cstdint>

#define NN   100000
#define EE   1600000
#define IND  128
#define HIDD 256
#define OUTD 64
#define NB_SCAN 196   // ceil(NN/512)

// ---------------- scratch (device globals: allocation-free rule) -------------
__device__ int   g_src[EE];
__device__ int   g_dst[EE];
__device__ int   g_eidx[EE];
__device__ int   g_count[NN];
__device__ int   g_cursor[NN];
__device__ int   g_bsum[NB_SCAN];
__device__ int   g_off[NN + 1];
__device__ float g_inv[NN];
__device__ int   g_is64;

// fp16 operands
__device__ __align__(16) __half g_xh[NN * 128];    // x as fp16 (gather payload)
__device__ __align__(16) __half g_a1h[NN * 256];   // [mean|x] hi
__device__ __align__(16) __half g_a1l[NN * 256];   // [mean|x] lo
__device__ __align__(16) __half g_hh[NN * 256];    // h hi
__device__ __align__(16) __half g_hl[NN * 256];    // h lo
__device__ __align__(16) __half g_w1[256 * 256];
__device__ __align__(16) __half g_w2[128 * 256];
__device__ __align__(16) __half g_ph[NN * 64];     // p as fp16 (gather payload)
__device__ __align__(16) float  g_q[NN * 64];      // q fp32

// ---------------- helpers -----------------------------------------------------
__device__ __forceinline__ uint32_t smem_u32(const void* p) {
    uint32_t a;
    asm("{ .reg .u64 t; cvta.to.shared.u64 t, %1; cvt.u32.u64 %0, t; }"
        : "=r"(a) : "l"(p));
    return a;
}
__device__ __forceinline__ void ldsm4(uint32_t* r, uint32_t addr) {
    asm volatile("ldmatrix.sync.aligned.m8n8.x4.shared.b16 {%0,%1,%2,%3}, [%4];"
                 : "=r"(r[0]), "=r"(r[1]), "=r"(r[2]), "=r"(r[3]) : "r"(addr));
}
__device__ __forceinline__ void mma_f16(float* d, const uint32_t* a,
                                        uint32_t b0, uint32_t b1) {
    asm volatile(
        "mma.sync.aligned.m16n8k16.row.col.f32.f16.f16.f32 "
        "{%0,%1,%2,%3}, {%4,%5,%6,%7}, {%8,%9}, {%0,%1,%2,%3};"
        : "+f"(d[0]), "+f"(d[1]), "+f"(d[2]), "+f"(d[3])
        : "r"(a[0]), "r"(a[1]), "r"(a[2]), "r"(a[3]), "r"(b0), "r"(b1));
}
__device__ __forceinline__ void hsplit(float v, __half& h, __half& l) {
    h = __float2half_rn(v);
    l = __float2half_rn(v - __half2float(h));
}
__device__ __forceinline__ void cpasync16(uint32_t dst, const void* src, int srcsz) {
    asm volatile("cp.async.cg.shared.global [%0], [%1], 16, %2;"
                 :: "r"(dst), "l"(src), "r"(srcsz));
}
__device__ __forceinline__ void cp_commit() {
    asm volatile("cp.async.commit_group;");
}
__device__ __forceinline__ void cp_wait1() {
    asm volatile("cp.async.wait_group 1;");
}

// ---------------- index dtype detection ---------------------------------------
__global__ void k_detect(const void* __restrict__ ei) {
    __shared__ int s_any;
    if (threadIdx.x == 0) s_any = 0;
    __syncthreads();
    const uint2* p = (const uint2*)ei;
    unsigned any = 0;
    for (int i = threadIdx.x; i < 2048; i += blockDim.x) any |= p[i].y;
    if (any) atomicOr(&s_any, 1);
    __syncthreads();
    if (threadIdx.x == 0) g_is64 = (s_any == 0) ? 1 : 0;
}

__global__ void k_zero_cnt() {
    int t = blockIdx.x * blockDim.x + threadIdx.x;
    if (t < NN) { g_count[t] = 0; g_cursor[t] = 0; }
}

__global__ void k_convert(const void* __restrict__ ei) {
    int t = blockIdx.x * blockDim.x + threadIdx.x;
    if (t >= 2 * EE) return;
    int v;
    if (g_is64) v = (int)((const long long*)ei)[t];
    else        v = ((const int*)ei)[t];
    if (t < EE) g_src[t] = v;
    else { g_dst[t - EE] = v; atomicAdd(&g_count[v], 1); }
}

// ---------------- x -> fp16 (gather payload) -----------------------------------
__global__ void k_prep(const float* __restrict__ x) {
    int t = blockIdx.x * blockDim.x + threadIdx.x;
    if (t >= NN * 32) return;
    float4 v = ((const float4*)x)[t];
    __half2 a = __floats2half2_rn(v.x, v.y);
    __half2 b = __floats2half2_rn(v.z, v.w);
    uint2 o;
    o.x = *(uint32_t*)&a;
    o.y = *(uint32_t*)&b;
    ((uint2*)g_xh)[t] = o;
}

// ---------------- exclusive scan of g_count -> g_off --------------------------
__global__ void k_s1() {
    int t = blockIdx.x * 512 + threadIdx.x;
    int v = (t < NN) ? g_count[t] : 0;
    __shared__ int sw[16];
    int wid = threadIdx.x >> 5, lid = threadIdx.x & 31;
    int s = v;
#pragma unroll
    for (int o = 16; o > 0; o >>= 1) s += __shfl_down_sync(0xffffffff, s, o);
    if (lid == 0) sw[wid] = s;
    __syncthreads();
    if (wid == 0) {
        int x = (lid < 16) ? sw[lid] : 0;
#pragma unroll
        for (int o = 16; o > 0; o >>= 1) x += __shfl_down_sync(0xffffffff, x, o);
        if (lid == 0) g_bsum[blockIdx.x] = x;
    }
}
__global__ void k_s2() {
    if (threadIdx.x == 0) {
        int run = 0;
        for (int i = 0; i < NB_SCAN; i++) { int v = g_bsum[i]; g_bsum[i] = run; run += v; }
        g_off[NN] = run;
    }
}
__global__ void k_s3() {
    __shared__ int sm[512];
    int t = blockIdx.x * 512 + threadIdx.x;
    int v = (t < NN) ? g_count[t] : 0;
    sm[threadIdx.x] = v;
    __syncthreads();
#pragma unroll
    for (int o = 1; o < 512; o <<= 1) {
        int tmp = (threadIdx.x >= o) ? sm[threadIdx.x - o] : 0;
        __syncthreads();
        sm[threadIdx.x] += tmp;
        __syncthreads();
    }
    if (t < NN) g_off[t] = sm[threadIdx.x] - v + g_bsum[blockIdx.x];
}

__global__ void k_build() {
    int t = blockIdx.x * blockDim.x + threadIdx.x;
    if (t >= EE) return;
    int d = g_dst[t];
    int p = g_off[d] + atomicAdd(&g_cursor[d], 1);
    g_eidx[p] = g_src[t];
}

// ---------------- weight convert (runs once, tiny) -----------------------------
__global__ void k_splitw(const float* __restrict__ W1l, const float* __restrict__ W1r,
                         const float* __restrict__ W2l, const float* __restrict__ W2r) {
    int t = blockIdx.x * blockDim.x + threadIdx.x;
    if (t < 256 * 256) {
        int row = t >> 8, k = t & 255;
        float v = (k < 128) ? W1l[row * 128 + k] : W1r[row * 128 + (k - 128)];
        g_w1[t] = __float2half_rn(v);
    } else if (t < 256 * 256 + 128 * 256) {
        int u = t - 256 * 256;
        int row = u >> 8, k = u & 255;
        float v = (row < 64) ? W2l[row * 256 + k] : W2r[(row - 64) * 256 + k];
        g_w2[u] = __float2half_rn(v);
    }
}

// ---------------- layer-1 segmented mean + split: warp per node ----------------
// Gathers fp16 x rows (256B) instead of fp32 (512B); accumulates fp32.
__global__ void k_reduce1(const float* __restrict__ x) {
    int wgl = (blockIdx.x * blockDim.x + threadIdx.x) >> 5;
    int lane = threadIdx.x & 31;
    if (wgl >= NN) return;
    int beg = g_off[wgl], end = g_off[wgl + 1];
    float4 acc = make_float4(0.f, 0.f, 0.f, 0.f);
    for (int base = beg; base < end; base += 32) {
        int rem = end - base;
        int eid = (lane < rem) ? g_eidx[base + lane] : 0;
        int cnt = rem < 32 ? rem : 32;
#pragma unroll 4
        for (int j = 0; j < cnt; j++) {
            int s = __shfl_sync(0xffffffff, eid, j);
            uint2 u = ((const uint2*)g_xh)[s * 32 + lane];
            float2 f0 = __half22float2(*(__half2*)&u.x);
            float2 f1 = __half22float2(*(__half2*)&u.y);
            acc.x += f0.x; acc.y += f0.y; acc.z += f1.x; acc.w += f1.y;
        }
    }
    float inv = 1.0f / fmaxf((float)(end - beg), 1.0f);
    acc.x *= inv; acc.y *= inv; acc.z *= inv; acc.w *= inv;
    if (lane == 0) g_inv[wgl] = inv;

    __half h[4], l[4];
    hsplit(acc.x, h[0], l[0]); hsplit(acc.y, h[1], l[1]);
    hsplit(acc.z, h[2], l[2]); hsplit(acc.w, h[3], l[3]);
    *(ushort4*)(g_a1h + wgl * 256 + lane * 4) = *(ushort4*)h;
    *(ushort4*)(g_a1l + wgl * 256 + lane * 4) = *(ushort4*)l;
    // root path: exact fp32 x row, split hi/lo
    float4 xv = ((const float4*)x)[wgl * 32 + lane];
    hsplit(xv.x, h[0], l[0]); hsplit(xv.y, h[1], l[1]);
    hsplit(xv.z, h[2], l[2]); hsplit(xv.w, h[3], l[3]);
    *(ushort4*)(g_a1h + wgl * 256 + 128 + lane * 4) = *(ushort4*)h;
    *(ushort4*)(g_a1l + wgl * 256 + 128 + lane * 4) = *(ushort4*)l;
}

// ======================= pipelined fp16 2-term mma.sync GEMM =================
// MODE 0: h = relu(A1 @ W1^T + b1)   N=256 (grid.y=2)
// MODE 1: p(fp16)|q(fp32) = H @ W2^T N=128 (grid.y=1)
#define STG   24576
#define OP_AH 0
#define OP_AL 8192
#define OP_BH 16384

template <int MODE>
__global__ __launch_bounds__(256) void k_gemm_mma(const float* __restrict__ bias)
{
    extern __shared__ char smem[];
    const uint32_t sb = smem_u32(smem);

    const int tid  = threadIdx.x;
    const int wid  = tid >> 5;
    const int lane = tid & 31;
    const int wm   = wid & 3;
    const int wn   = wid >> 2;
    const int m0   = blockIdx.x * 128;
    const int j0   = blockIdx.y * 128;

    const __half* Ah = (MODE == 0) ? g_a1h : g_hh;
    const __half* Al = (MODE == 0) ? g_a1l : g_hl;
    const __half* Bh = (MODE == 0) ? g_w1 : g_w2;

    float acc[2][8][4];
#pragma unroll
    for (int a = 0; a < 2; a++)
#pragma unroll
        for (int b = 0; b < 8; b++)
#pragma unroll
            for (int c = 0; c < 4; c++) acc[a][b][c] = 0.f;

    const int r8   = lane & 7;
    const int subm = lane >> 3;

    auto load_chunk = [&](int ch, int s) {
        const int kt = ch * 32;
        const uint32_t sbase = sb + s * STG;
#pragma unroll
        for (int i = 0; i < 2; i++) {
            int idx = tid + i * 256;            // 0..511
            int row = idx >> 2;                 // 0..127
            int c   = idx & 3;                  // 16B chunk along k
            uint32_t off = (uint32_t)(row * 64 + ((c ^ ((row >> 1) & 3)) * 16));
            int gr = m0 + row;
            int szA = (gr < NN) ? 16 : 0;
            const __half* pa = Ah + (size_t)gr * 256 + kt + c * 8;
            const __half* pl = Al + (size_t)gr * 256 + kt + c * 8;
            if (gr >= NN) { pa = Ah; pl = Al; }   // safe address, zfilled
            cpasync16(sbase + OP_AH + off, pa, szA);
            cpasync16(sbase + OP_AL + off, pl, szA);
            cpasync16(sbase + OP_BH + off, Bh + (size_t)(j0 + row) * 256 + kt + c * 8, 16);
        }
    };

    load_chunk(0, 0);
    cp_commit();

    for (int ch = 0; ch < 8; ch++) {
        if (ch < 7) load_chunk(ch + 1, (ch + 1) & 1);
        cp_commit();                  // (empty group on last iter)
        cp_wait1();
        __syncthreads();

        const uint32_t sbase = sb + (ch & 1) * STG;
#pragma unroll
        for (int ks = 0; ks < 2; ks++) {
            const int cb = ks * 2;
            uint32_t ahf[2][4], alf[2][4];
#pragma unroll
            for (int tm = 0; tm < 2; tm++) {
                int arow = wm * 32 + tm * 16 + (subm & 1) * 8 + r8;
                int achk = cb + (subm >> 1);
                uint32_t ab = (uint32_t)(arow * 64 + ((achk ^ ((arow >> 1) & 3)) * 16));
                ldsm4(ahf[tm], sbase + OP_AH + ab);
                ldsm4(alf[tm], sbase + OP_AL + ab);
            }
            uint32_t bh[16];
#pragma unroll
            for (int g = 0; g < 4; g++) {
                int brow = wn * 64 + g * 16 + (subm >> 1) * 8 + r8;
                int bchk = cb + (subm & 1);
                uint32_t bb = (uint32_t)(brow * 64 + ((bchk ^ ((brow >> 1) & 3)) * 16));
                ldsm4(&bh[g * 4], sbase + OP_BH + bb);
            }
#pragma unroll
            for (int tm = 0; tm < 2; tm++)
#pragma unroll
                for (int tn = 0; tn < 8; tn++) {
                    mma_f16(acc[tm][tn], ahf[tm], bh[tn * 2], bh[tn * 2 + 1]);
                    mma_f16(acc[tm][tn], alf[tm], bh[tn * 2], bh[tn * 2 + 1]);
                }
        }
        __syncthreads();
    }

    // ---- epilogue --------------------------------------------------------------
    const int qrow = lane >> 2;
    const int qcol = (lane & 3) * 2;
#pragma unroll
    for (int tm = 0; tm < 2; tm++) {
#pragma unroll
        for (int half = 0; half < 2; half++) {
            int gr = m0 + wm * 32 + tm * 16 + half * 8 + qrow;
            if (gr >= NN) continue;
#pragma unroll
            for (int tn = 0; tn < 8; tn++) {
                int gc = j0 + wn * 64 + tn * 8 + qcol;
                float v0 = acc[tm][tn][half * 2 + 0];
                float v1 = acc[tm][tn][half * 2 + 1];
                if (MODE == 0) {
                    v0 = fmaxf(v0 + bias[gc], 0.f);
                    v1 = fmaxf(v1 + bias[gc + 1], 0.f);
                    __half h0, l0, h1, l1;
                    hsplit(v0, h0, l0);
                    hsplit(v1, h1, l1);
                    __half hp[2] = {h0, h1}, lp[2] = {l0, l1};
                    *(uint32_t*)(g_hh + gr * 256 + gc) = *(uint32_t*)hp;
                    *(uint32_t*)(g_hl + gr * 256 + gc) = *(uint32_t*)lp;
                } else {
                    if (gc < 64) {   // p half: store fp16
                        __half2 hv = __floats2half2_rn(v0, v1);
                        *(__half2*)(g_ph + gr * 64 + gc) = hv;
                    } else {         // q half: store fp32
                        *(float2*)(g_q + gr * 64 + (gc - 64)) = make_float2(v0, v1);
                    }
                }
            }
        }
    }
}

// ---------------- layer-2 segmented mean + epilogue: warp per node ------------
// Gathers fp16 p rows (128B); accumulates fp32.
__global__ void k_reduce2(const float* __restrict__ b2, float* __restrict__ out) {
    int wgl = (blockIdx.x * blockDim.x + threadIdx.x) >> 5;
    int lane = threadIdx.x & 31;
    if (wgl >= NN) return;
    int beg = g_off[wgl], end = g_off[wgl + 1];
    float2 acc = make_float2(0.f, 0.f);
    for (int base = beg; base < end; base += 32) {
        int rem = end - base;
        int eid = (lane < rem) ? g_eidx[base + lane] : 0;
        int cnt = rem < 32 ? rem : 32;
#pragma unroll 4
        for (int j = 0; j < cnt; j++) {
            int s = __shfl_sync(0xffffffff, eid, j);
            __half2 hv = ((const __half2*)g_ph)[s * 32 + lane];
            float2 f = __half22float2(hv);
            acc.x += f.x; acc.y += f.y;
        }
    }
    float inv = g_inv[wgl];
    float2 q  = ((const float2*)g_q)[wgl * 32 + lane];
    float2 bb = ((const float2*)b2)[lane];
    float2 r;
    r.x = fmaf(acc.x, inv, bb.x) + q.x;
    r.y = fmaf(acc.y, inv, bb.y) + q.y;
    ((float2*)out)[wgl * 32 + lane] = r;
}

// ---------------- launch ------------------------------------------------------
extern "C" void kernel_launch(void* const* d_in, const int* in_sizes, int n_in,
                              void* d_out, int out_size) {
    const float* x   = (const float*)d_in[0];
    const void*  ei  = d_in[1];
    const float* W1l = (const float*)d_in[2];
    const float* b1  = (const float*)d_in[3];
    const float* W1r = (const float*)d_in[4];
    const float* W2l = (const float*)d_in[5];
    const float* b2  = (const float*)d_in[6];
    const float* W2r = (const float*)d_in[7];
    float* out = (float*)d_out;

    const int SMEM = 2 * STG;   // 49152
    cudaFuncSetAttribute(k_gemm_mma<0>,
                         cudaFuncAttributeMaxDynamicSharedMemorySize, SMEM);
    cudaFuncSetAttribute(k_gemm_mma<1>,
                         cudaFuncAttributeMaxDynamicSharedMemorySize, SMEM);

    k_detect<<<1, 256>>>(ei);
    k_zero_cnt<<<(NN + 255) / 256, 256>>>();
    k_convert<<<(2 * EE + 255) / 256, 256>>>(ei);
    k_prep<<<(NN * 32 + 255) / 256, 256>>>(x);
    k_splitw<<<(256 * 256 + 128 * 256 + 255) / 256, 256>>>(W1l, W1r, W2l, W2r);

    k_s1<<<NB_SCAN, 512>>>();
    k_s2<<<1, 32>>>();
    k_s3<<<NB_SCAN, 512>>>();
    k_build<<<(EE + 255) / 256, 256>>>();

    k_reduce1<<<(NN * 32 + 255) / 256, 256>>>(x);

    const int MT = (NN + 127) / 128;   // 782
    k_gemm_mma<0><<<dim3(MT, 2), 256, SMEM>>>(b1);
    k_gemm_mma<1><<<dim3(MT, 1), 256, SMEM>>>(b1);

    k_reduce2<<<(NN * 32 + 255) / 256, 256>>>(b2, out);
}

// round 13
// speedup vs baseline: 1.5292x; 1.4184x over previous
#include <cuda_runtime.h>
#include <cuda_fp16.h>
#include <cstdint>

#define NN   100000
#define EE   1600000
#define IND  128
#define HIDD 256
#define OUTD 64
#define NB_SCAN 196   // ceil(NN/512)

// ---------------- scratch (device globals: allocation-free rule) -------------
__device__ int   g_src[EE];
__device__ int   g_dst[EE];
__device__ int   g_eidx[EE];
__device__ int   g_count[NN];
__device__ int   g_cursor[NN];
__device__ int   g_bsum[NB_SCAN];
__device__ int   g_off[NN + 1];
__device__ float g_inv[NN];
__device__ int   g_is64;

// fp16 operands (single-term: fp32 accumulate, fp16 inputs)
__device__ __align__(16) __half g_xh[NN * 128];    // x fp16 (gather payload + gemm1 A right half)
__device__ __align__(16) __half g_a1[NN * 128];    // mean fp16 (gemm1 A left half)
__device__ __align__(16) __half g_h[NN * 256];     // h fp16
__device__ __align__(16) __half g_w1[256 * 256];
__device__ __align__(16) __half g_w2[128 * 256];
__device__ __align__(16) __half g_ph[NN * 64];     // p fp16 (gather payload)
__device__ __align__(16) float  g_q[NN * 64];      // q fp32

// ---------------- helpers -----------------------------------------------------
__device__ __forceinline__ uint32_t smem_u32(const void* p) {
    uint32_t a;
    asm("{ .reg .u64 t; cvta.to.shared.u64 t, %1; cvt.u32.u64 %0, t; }"
        : "=r"(a) : "l"(p));
    return a;
}
__device__ __forceinline__ void ldsm4(uint32_t* r, uint32_t addr) {
    asm volatile("ldmatrix.sync.aligned.m8n8.x4.shared.b16 {%0,%1,%2,%3}, [%4];"
                 : "=r"(r[0]), "=r"(r[1]), "=r"(r[2]), "=r"(r[3]) : "r"(addr));
}
__device__ __forceinline__ void mma_f16(float* d, const uint32_t* a,
                                        uint32_t b0, uint32_t b1) {
    asm volatile(
        "mma.sync.aligned.m16n8k16.row.col.f32.f16.f16.f32 "
        "{%0,%1,%2,%3}, {%4,%5,%6,%7}, {%8,%9}, {%0,%1,%2,%3};"
        : "+f"(d[0]), "+f"(d[1]), "+f"(d[2]), "+f"(d[3])
        : "r"(a[0]), "r"(a[1]), "r"(a[2]), "r"(a[3]), "r"(b0), "r"(b1));
}
__device__ __forceinline__ void cpasync16(uint32_t dst, const void* src, int srcsz) {
    asm volatile("cp.async.cg.shared.global [%0], [%1], 16, %2;"
                 :: "r"(dst), "l"(src), "r"(srcsz));
}
__device__ __forceinline__ void cp_commit() {
    asm volatile("cp.async.commit_group;");
}
__device__ __forceinline__ void cp_wait1() {
    asm volatile("cp.async.wait_group 1;");
}

// ---------------- index dtype detection ---------------------------------------
__global__ void k_detect(const void* __restrict__ ei) {
    __shared__ int s_any;
    if (threadIdx.x == 0) s_any = 0;
    __syncthreads();
    const uint2* p = (const uint2*)ei;
    unsigned any = 0;
    for (int i = threadIdx.x; i < 2048; i += blockDim.x) any |= p[i].y;
    if (any) atomicOr(&s_any, 1);
    __syncthreads();
    if (threadIdx.x == 0) g_is64 = (s_any == 0) ? 1 : 0;
}

__global__ void k_zero_cnt() {
    int t = blockIdx.x * blockDim.x + threadIdx.x;
    if (t < NN) { g_count[t] = 0; g_cursor[t] = 0; }
}

__global__ void k_convert(const void* __restrict__ ei) {
    int t = blockIdx.x * blockDim.x + threadIdx.x;
    if (t >= 2 * EE) return;
    int v;
    if (g_is64) v = (int)((const long long*)ei)[t];
    else        v = ((const int*)ei)[t];
    if (t < EE) g_src[t] = v;
    else { g_dst[t - EE] = v; atomicAdd(&g_count[v], 1); }
}

// ---------------- x -> fp16 ----------------------------------------------------
__global__ void k_prep(const float* __restrict__ x) {
    int t = blockIdx.x * blockDim.x + threadIdx.x;
    if (t >= NN * 32) return;
    float4 v = ((const float4*)x)[t];
    __half2 a = __floats2half2_rn(v.x, v.y);
    __half2 b = __floats2half2_rn(v.z, v.w);
    uint2 o;
    o.x = *(uint32_t*)&a;
    o.y = *(uint32_t*)&b;
    ((uint2*)g_xh)[t] = o;
}

// ---------------- exclusive scan of g_count -> g_off --------------------------
__global__ void k_s1() {
    int t = blockIdx.x * 512 + threadIdx.x;
    int v = (t < NN) ? g_count[t] : 0;
    __shared__ int sw[16];
    int wid = threadIdx.x >> 5, lid = threadIdx.x & 31;
    int s = v;
#pragma unroll
    for (int o = 16; o > 0; o >>= 1) s += __shfl_down_sync(0xffffffff, s, o);
    if (lid == 0) sw[wid] = s;
    __syncthreads();
    if (wid == 0) {
        int x = (lid < 16) ? sw[lid] : 0;
#pragma unroll
        for (int o = 16; o > 0; o >>= 1) x += __shfl_down_sync(0xffffffff, x, o);
        if (lid == 0) g_bsum[blockIdx.x] = x;
    }
}
__global__ void k_s2() {
    if (threadIdx.x == 0) {
        int run = 0;
        for (int i = 0; i < NB_SCAN; i++) { int v = g_bsum[i]; g_bsum[i] = run; run += v; }
        g_off[NN] = run;
    }
}
__global__ void k_s3() {
    __shared__ int sm[512];
    int t = blockIdx.x * 512 + threadIdx.x;
    int v = (t < NN) ? g_count[t] : 0;
    sm[threadIdx.x] = v;
    __syncthreads();
#pragma unroll
    for (int o = 1; o < 512; o <<= 1) {
        int tmp = (threadIdx.x >= o) ? sm[threadIdx.x - o] : 0;
        __syncthreads();
        sm[threadIdx.x] += tmp;
        __syncthreads();
    }
    if (t < NN) g_off[t] = sm[threadIdx.x] - v + g_bsum[blockIdx.x];
}

__global__ void k_build() {
    int t = blockIdx.x * blockDim.x + threadIdx.x;
    if (t >= EE) return;
    int d = g_dst[t];
    int p = g_off[d] + atomicAdd(&g_cursor[d], 1);
    g_eidx[p] = g_src[t];
}

// ---------------- weight convert (runs once, tiny) -----------------------------
__global__ void k_splitw(const float* __restrict__ W1l, const float* __restrict__ W1r,
                         const float* __restrict__ W2l, const float* __restrict__ W2r) {
    int t = blockIdx.x * blockDim.x + threadIdx.x;
    if (t < 256 * 256) {
        int row = t >> 8, k = t & 255;
        float v = (k < 128) ? W1l[row * 128 + k] : W1r[row * 128 + (k - 128)];
        g_w1[t] = __float2half_rn(v);
    } else if (t < 256 * 256 + 128 * 256) {
        int u = t - 256 * 256;
        int row = u >> 8, k = u & 255;
        float v = (row < 64) ? W2l[row * 256 + k] : W2r[(row - 64) * 256 + k];
        g_w2[u] = __float2half_rn(v);
    }
}

// ---------------- layer-1 segmented mean: warp per node ------------------------
// Gathers fp16 x rows (256B); fp32 accumulate; writes mean as fp16.
__global__ void k_reduce1() {
    int wgl = (blockIdx.x * blockDim.x + threadIdx.x) >> 5;
    int lane = threadIdx.x & 31;
    if (wgl >= NN) return;
    int beg = g_off[wgl], end = g_off[wgl + 1];
    float4 acc = make_float4(0.f, 0.f, 0.f, 0.f);
    for (int base = beg; base < end; base += 32) {
        int rem = end - base;
        int eid = (lane < rem) ? g_eidx[base + lane] : 0;
        int cnt = rem < 32 ? rem : 32;
#pragma unroll 4
        for (int j = 0; j < cnt; j++) {
            int s = __shfl_sync(0xffffffff, eid, j);
            uint2 u = ((const uint2*)g_xh)[s * 32 + lane];
            float2 f0 = __half22float2(*(__half2*)&u.x);
            float2 f1 = __half22float2(*(__half2*)&u.y);
            acc.x += f0.x; acc.y += f0.y; acc.z += f1.x; acc.w += f1.y;
        }
    }
    float inv = 1.0f / fmaxf((float)(end - beg), 1.0f);
    if (lane == 0) g_inv[wgl] = inv;
    __half2 a = __floats2half2_rn(acc.x * inv, acc.y * inv);
    __half2 b = __floats2half2_rn(acc.z * inv, acc.w * inv);
    uint2 o;
    o.x = *(uint32_t*)&a;
    o.y = *(uint32_t*)&b;
    ((uint2*)g_a1)[wgl * 32 + lane] = o;
}

// ======================= pipelined single-term fp16 mma.sync GEMM ============
// MODE 0: h = relu([mean|x] @ W1^T + b1)   A left=g_a1, right=g_xh; N=256 (grid.y=2)
// MODE 1: p(fp16)|q(fp32) = H @ W2^T       A=g_h; N=128 (grid.y=1)
#define STG   16384
#define OP_A  0
#define OP_B  8192

template <int MODE>
__global__ __launch_bounds__(256) void k_gemm_mma(const float* __restrict__ bias)
{
    extern __shared__ char smem[];
    const uint32_t sb = smem_u32(smem);

    const int tid  = threadIdx.x;
    const int wid  = tid >> 5;
    const int lane = tid & 31;
    const int wm   = wid & 3;
    const int wn   = wid >> 2;
    const int m0   = blockIdx.x * 128;
    const int j0   = blockIdx.y * 128;

    const __half* Bw = (MODE == 0) ? g_w1 : g_w2;

    float acc[2][8][4];
#pragma unroll
    for (int a = 0; a < 2; a++)
#pragma unroll
        for (int b = 0; b < 8; b++)
#pragma unroll
            for (int c = 0; c < 4; c++) acc[a][b][c] = 0.f;

    const int r8   = lane & 7;
    const int subm = lane >> 3;

    auto load_chunk = [&](int ch, int s) {
        const int kt = ch * 32;
        const uint32_t sbase = sb + s * STG;
#pragma unroll
        for (int i = 0; i < 2; i++) {
            int idx = tid + i * 256;            // 0..511
            int row = idx >> 2;                 // 0..127
            int c   = idx & 3;                  // 16B chunk along k
            uint32_t off = (uint32_t)(row * 64 + ((c ^ ((row >> 1) & 3)) * 16));
            int gr = m0 + row;
            int szA = (gr < NN) ? 16 : 0;
            const __half* pa;
            if (MODE == 0) {
                // A = [mean | x] : left half from g_a1, right half from g_xh
                pa = (kt < 128) ? (g_a1 + (size_t)gr * 128 + kt + c * 8)
                                : (g_xh + (size_t)gr * 128 + (kt - 128) + c * 8);
                if (gr >= NN) pa = g_a1;
            } else {
                pa = g_h + (size_t)gr * 256 + kt + c * 8;
                if (gr >= NN) pa = g_h;
            }
            cpasync16(sbase + OP_A + off, pa, szA);
            cpasync16(sbase + OP_B + off, Bw + (size_t)(j0 + row) * 256 + kt + c * 8, 16);
        }
    };

    load_chunk(0, 0);
    cp_commit();

    for (int ch = 0; ch < 8; ch++) {
        if (ch < 7) load_chunk(ch + 1, (ch + 1) & 1);
        cp_commit();                  // (empty group on last iter)
        cp_wait1();
        __syncthreads();

        const uint32_t sbase = sb + (ch & 1) * STG;
#pragma unroll
        for (int ks = 0; ks < 2; ks++) {
            const int cb = ks * 2;
            uint32_t af[2][4];
#pragma unroll
            for (int tm = 0; tm < 2; tm++) {
                int arow = wm * 32 + tm * 16 + (subm & 1) * 8 + r8;
                int achk = cb + (subm >> 1);
                uint32_t ab = (uint32_t)(arow * 64 + ((achk ^ ((arow >> 1) & 3)) * 16));
                ldsm4(af[tm], sbase + OP_A + ab);
            }
            uint32_t bh[16];
#pragma unroll
            for (int g = 0; g < 4; g++) {
                int brow = wn * 64 + g * 16 + (subm >> 1) * 8 + r8;
                int bchk = cb + (subm & 1);
                uint32_t bb = (uint32_t)(brow * 64 + ((bchk ^ ((brow >> 1) & 3)) * 16));
                ldsm4(&bh[g * 4], sbase + OP_B + bb);
            }
#pragma unroll
            for (int tm = 0; tm < 2; tm++)
#pragma unroll
                for (int tn = 0; tn < 8; tn++)
                    mma_f16(acc[tm][tn], af[tm], bh[tn * 2], bh[tn * 2 + 1]);
        }
        __syncthreads();
    }

    // ---- epilogue --------------------------------------------------------------
    const int qrow = lane >> 2;
    const int qcol = (lane & 3) * 2;
#pragma unroll
    for (int tm = 0; tm < 2; tm++) {
#pragma unroll
        for (int half = 0; half < 2; half++) {
            int gr = m0 + wm * 32 + tm * 16 + half * 8 + qrow;
            if (gr >= NN) continue;
#pragma unroll
            for (int tn = 0; tn < 8; tn++) {
                int gc = j0 + wn * 64 + tn * 8 + qcol;
                float v0 = acc[tm][tn][half * 2 + 0];
                float v1 = acc[tm][tn][half * 2 + 1];
                if (MODE == 0) {
                    v0 = fmaxf(v0 + bias[gc], 0.f);
                    v1 = fmaxf(v1 + bias[gc + 1], 0.f);
                    __half2 hv = __floats2half2_rn(v0, v1);
                    *(__half2*)(g_h + gr * 256 + gc) = hv;
                } else {
                    if (gc < 64) {   // p half: fp16
                        __half2 hv = __floats2half2_rn(v0, v1);
                        *(__half2*)(g_ph + gr * 64 + gc) = hv;
                    } else {         // q half: fp32
                        *(float2*)(g_q + gr * 64 + (gc - 64)) = make_float2(v0, v1);
                    }
                }
            }
        }
    }
}

// ---------------- layer-2 segmented mean + epilogue: warp per node ------------
__global__ void k_reduce2(const float* __restrict__ b2, float* __restrict__ out) {
    int wgl = (blockIdx.x * blockDim.x + threadIdx.x) >> 5;
    int lane = threadIdx.x & 31;
    if (wgl >= NN) return;
    int beg = g_off[wgl], end = g_off[wgl + 1];
    float2 acc = make_float2(0.f, 0.f);
    for (int base = beg; base < end; base += 32) {
        int rem = end - base;
        int eid = (lane < rem) ? g_eidx[base + lane] : 0;
        int cnt = rem < 32 ? rem : 32;
#pragma unroll 4
        for (int j = 0; j < cnt; j++) {
            int s = __shfl_sync(0xffffffff, eid, j);
            __half2 hv = ((const __half2*)g_ph)[s * 32 + lane];
            float2 f = __half22float2(hv);
            acc.x += f.x; acc.y += f.y;
        }
    }
    float inv = g_inv[wgl];
    float2 q  = ((const float2*)g_q)[wgl * 32 + lane];
    float2 bb = ((const float2*)b2)[lane];
    float2 r;
    r.x = fmaf(acc.x, inv, bb.x) + q.x;
    r.y = fmaf(acc.y, inv, bb.y) + q.y;
    ((float2*)out)[wgl * 32 + lane] = r;
}

// ---------------- launch ------------------------------------------------------
extern "C" void kernel_launch(void* const* d_in, const int* in_sizes, int n_in,
                              void* d_out, int out_size) {
    const float* x   = (const float*)d_in[0];
    const void*  ei  = d_in[1];
    const float* W1l = (const float*)d_in[2];
    const float* b1  = (const float*)d_in[3];
    const float* W1r = (const float*)d_in[4];
    const float* W2l = (const float*)d_in[5];
    const float* b2  = (const float*)d_in[6];
    const float* W2r = (const float*)d_in[7];
    float* out = (float*)d_out;

    const int SMEM = 2 * STG;   // 32768
    cudaFuncSetAttribute(k_gemm_mma<0>,
                         cudaFuncAttributeMaxDynamicSharedMemorySize, SMEM);
    cudaFuncSetAttribute(k_gemm_mma<1>,
                         cudaFuncAttributeMaxDynamicSharedMemorySize, SMEM);

    k_detect<<<1, 256>>>(ei);
    k_zero_cnt<<<(NN + 255) / 256, 256>>>();
    k_convert<<<(2 * EE + 255) / 256, 256>>>(ei);
    k_prep<<<(NN * 32 + 255) / 256, 256>>>(x);
    k_splitw<<<(256 * 256 + 128 * 256 + 255) / 256, 256>>>(W1l, W1r, W2l, W2r);

    k_s1<<<NB_SCAN, 512>>>();
    k_s2<<<1, 32>>>();
    k_s3<<<NB_SCAN, 512>>>();
    k_build<<<(EE + 255) / 256, 256>>>();

    k_reduce1<<<(NN * 32 + 255) / 256, 256>>>();

    const int MT = (NN + 127) / 128;   // 782
    k_gemm_mma<0><<<dim3(MT, 2), 256, SMEM>>>(b1);
    k_gemm_mma<1><<<dim3(MT, 1), 256, SMEM>>>(b1);

    k_reduce2<<<(NN * 32 + 255) / 256, 256>>>(b2, out);
}

// round 14
// speedup vs baseline: 1.5502x; 1.0137x over previous
#include <cuda_runtime.h>
#include <cuda_fp16.h>
#include <cstdint>

#define NN   100000
#define EE   1600000
#define IND  128
#define HIDD 256
#define OUTD 64
#define NB_SCAN 196   // ceil(NN/512)

// ---------------- scratch (device globals: allocation-free rule) -------------
__device__ int      g_src[EE];
__device__ int      g_dst[EE];
__device__ uint16_t g_rank[EE];          // rank of edge within its dst bucket
__device__ int      g_eidx[EE];
__device__ int      g_count[NN];
__device__ int      g_bsum[NB_SCAN];
__device__ int      g_off[NN + 1];
__device__ float    g_inv[NN];
__device__ int      g_is64;

// fp16 operands (single-term: fp32 accumulate, fp16 inputs)
__device__ __align__(16) __half g_xh[NN * 128];    // x fp16
__device__ __align__(16) __half g_a1[NN * 128];    // mean fp16
__device__ __align__(16) __half g_h[NN * 256];     // h fp16
__device__ __align__(16) __half g_w1[256 * 256];
__device__ __align__(16) __half g_w2[128 * 256];
__device__ __align__(16) __half g_ph[NN * 64];     // p fp16
__device__ __align__(16) float  g_q[NN * 64];      // q fp32

// ---------------- helpers -----------------------------------------------------
__device__ __forceinline__ uint32_t smem_u32(const void* p) {
    uint32_t a;
    asm("{ .reg .u64 t; cvta.to.shared.u64 t, %1; cvt.u32.u64 %0, t; }"
        : "=r"(a) : "l"(p));
    return a;
}
__device__ __forceinline__ void ldsm4(uint32_t* r, uint32_t addr) {
    asm volatile("ldmatrix.sync.aligned.m8n8.x4.shared.b16 {%0,%1,%2,%3}, [%4];"
                 : "=r"(r[0]), "=r"(r[1]), "=r"(r[2]), "=r"(r[3]) : "r"(addr));
}
__device__ __forceinline__ void mma_f16(float* d, const uint32_t* a,
                                        uint32_t b0, uint32_t b1) {
    asm volatile(
        "mma.sync.aligned.m16n8k16.row.col.f32.f16.f16.f32 "
        "{%0,%1,%2,%3}, {%4,%5,%6,%7}, {%8,%9}, {%0,%1,%2,%3};"
        : "+f"(d[0]), "+f"(d[1]), "+f"(d[2]), "+f"(d[3])
        : "r"(a[0]), "r"(a[1]), "r"(a[2]), "r"(a[3]), "r"(b0), "r"(b1));
}
__device__ __forceinline__ void cpasync16(uint32_t dst, const void* src, int srcsz) {
    asm volatile("cp.async.cg.shared.global [%0], [%1], 16, %2;"
                 :: "r"(dst), "l"(src), "r"(srcsz));
}
__device__ __forceinline__ void cp_commit() {
    asm volatile("cp.async.commit_group;");
}
__device__ __forceinline__ void cp_wait1() {
    asm volatile("cp.async.wait_group 1;");
}

// ---------------- index dtype detection ---------------------------------------
__global__ void k_detect(const void* __restrict__ ei) {
    __shared__ int s_any;
    if (threadIdx.x == 0) s_any = 0;
    __syncthreads();
    const uint2* p = (const uint2*)ei;
    unsigned any = 0;
    for (int i = threadIdx.x; i < 2048; i += blockDim.x) any |= p[i].y;
    if (any) atomicOr(&s_any, 1);
    __syncthreads();
    if (threadIdx.x == 0) g_is64 = (s_any == 0) ? 1 : 0;
}

__global__ void k_zero_cnt() {
    int t = blockIdx.x * blockDim.x + threadIdx.x;
    if (t < NN) g_count[t] = 0;
}

// convert + histogram; atomic return value = rank within dst bucket
__global__ void k_convert(const void* __restrict__ ei) {
    int t = blockIdx.x * blockDim.x + threadIdx.x;
    if (t >= 2 * EE) return;
    int v;
    if (g_is64) v = (int)((const long long*)ei)[t];
    else        v = ((const int*)ei)[t];
    if (t < EE) g_src[t] = v;
    else {
        int e = t - EE;
        g_dst[e] = v;
        int r = atomicAdd(&g_count[v], 1);
        g_rank[e] = (uint16_t)r;
    }
}

// ---------------- x -> fp16 AND weight -> fp16 (fused, runs once) --------------
#define PREP_X  (NN * 32)                       // uint2 elements of x
#define PREP_W1 (256 * 256 / 8)                 // 8 halfs per thread
#define PREP_W2 (128 * 256 / 8)
__global__ void k_prep(const float* __restrict__ x,
                       const float* __restrict__ W1l, const float* __restrict__ W1r,
                       const float* __restrict__ W2l, const float* __restrict__ W2r) {
    int t = blockIdx.x * blockDim.x + threadIdx.x;
    if (t < PREP_X) {
        float4 v = ((const float4*)x)[t];
        __half2 a = __floats2half2_rn(v.x, v.y);
        __half2 b = __floats2half2_rn(v.z, v.w);
        uint2 o; o.x = *(uint32_t*)&a; o.y = *(uint32_t*)&b;
        ((uint2*)g_xh)[t] = o;
    } else if (t < PREP_X + PREP_W1) {
        int u = (t - PREP_X) * 8;               // base half index in g_w1
        int row = u >> 8, k = u & 255;
#pragma unroll
        for (int j = 0; j < 8; j++) {
            int kk = k + j;
            float v = (kk < 128) ? W1l[row * 128 + kk] : W1r[row * 128 + (kk - 128)];
            g_w1[u + j] = __float2half_rn(v);
        }
    } else if (t < PREP_X + PREP_W1 + PREP_W2) {
        int u = (t - PREP_X - PREP_W1) * 8;
        int row = u >> 8, k = u & 255;
#pragma unroll
        for (int j = 0; j < 8; j++) {
            float v = (row < 64) ? W2l[row * 256 + k + j] : W2r[(row - 64) * 256 + k + j];
            g_w2[u + j] = __float2half_rn(v);
        }
    }
}

// ---------------- exclusive scan of g_count -> g_off --------------------------
__global__ void k_s1() {
    int t = blockIdx.x * 512 + threadIdx.x;
    int v = (t < NN) ? g_count[t] : 0;
    __shared__ int sw[16];
    int wid = threadIdx.x >> 5, lid = threadIdx.x & 31;
    int s = v;
#pragma unroll
    for (int o = 16; o > 0; o >>= 1) s += __shfl_down_sync(0xffffffff, s, o);
    if (lid == 0) sw[wid] = s;
    __syncthreads();
    if (wid == 0) {
        int x = (lid < 16) ? sw[lid] : 0;
#pragma unroll
        for (int o = 16; o > 0; o >>= 1) x += __shfl_down_sync(0xffffffff, x, o);
        if (lid == 0) g_bsum[blockIdx.x] = x;
    }
}
__global__ void k_s2() {
    if (threadIdx.x == 0) {
        int run = 0;
        for (int i = 0; i < NB_SCAN; i++) { int v = g_bsum[i]; g_bsum[i] = run; run += v; }
        g_off[NN] = run;
    }
}
__global__ void k_s3() {
    __shared__ int sm[512];
    int t = blockIdx.x * 512 + threadIdx.x;
    int v = (t < NN) ? g_count[t] : 0;
    sm[threadIdx.x] = v;
    __syncthreads();
#pragma unroll
    for (int o = 1; o < 512; o <<= 1) {
        int tmp = (threadIdx.x >= o) ? sm[threadIdx.x - o] : 0;
        __syncthreads();
        sm[threadIdx.x] += tmp;
        __syncthreads();
    }
    if (t < NN) g_off[t] = sm[threadIdx.x] - v + g_bsum[blockIdx.x];
}

// ---------------- CSR build: atomic-free (rank precomputed) --------------------
__global__ void k_build() {
    int t = blockIdx.x * blockDim.x + threadIdx.x;
    if (t >= EE) return;
    int d = g_dst[t];
    int p = g_off[d] + (int)g_rank[t];
    g_eidx[p] = g_src[t];
}

// ---------------- layer-1 segmented mean: warp per node ------------------------
__global__ void k_reduce1() {
    int wgl = (blockIdx.x * blockDim.x + threadIdx.x) >> 5;
    int lane = threadIdx.x & 31;
    if (wgl >= NN) return;
    int beg = g_off[wgl], end = g_off[wgl + 1];
    float4 acc = make_float4(0.f, 0.f, 0.f, 0.f);
    for (int base = beg; base < end; base += 32) {
        int rem = end - base;
        int eid = (lane < rem) ? g_eidx[base + lane] : 0;
        int cnt = rem < 32 ? rem : 32;
#pragma unroll 4
        for (int j = 0; j < cnt; j++) {
            int s = __shfl_sync(0xffffffff, eid, j);
            uint2 u = ((const uint2*)g_xh)[s * 32 + lane];
            float2 f0 = __half22float2(*(__half2*)&u.x);
            float2 f1 = __half22float2(*(__half2*)&u.y);
            acc.x += f0.x; acc.y += f0.y; acc.z += f1.x; acc.w += f1.y;
        }
    }
    float inv = 1.0f / fmaxf((float)(end - beg), 1.0f);
    if (lane == 0) g_inv[wgl] = inv;
    __half2 a = __floats2half2_rn(acc.x * inv, acc.y * inv);
    __half2 b = __floats2half2_rn(acc.z * inv, acc.w * inv);
    uint2 o; o.x = *(uint32_t*)&a; o.y = *(uint32_t*)&b;
    ((uint2*)g_a1)[wgl * 32 + lane] = o;
}

// ======================= pipelined single-term fp16 mma.sync GEMM ============
// MODE 0: h = relu([mean|x] @ W1^T + b1)   N=256 (grid.y=2)
// MODE 1: p(fp16)|q(fp32) = H @ W2^T       N=128 (grid.y=1)
#define STG   16384
#define OP_A  0
#define OP_B  8192

template <int MODE>
__global__ __launch_bounds__(256) void k_gemm_mma(const float* __restrict__ bias)
{
    extern __shared__ char smem[];
    const uint32_t sb = smem_u32(smem);

    const int tid  = threadIdx.x;
    const int wid  = tid >> 5;
    const int lane = tid & 31;
    const int wm   = wid & 3;
    const int wn   = wid >> 2;
    const int m0   = blockIdx.x * 128;
    const int j0   = blockIdx.y * 128;

    const __half* Bw = (MODE == 0) ? g_w1 : g_w2;

    float acc[2][8][4];
#pragma unroll
    for (int a = 0; a < 2; a++)
#pragma unroll
        for (int b = 0; b < 8; b++)
#pragma unroll
            for (int c = 0; c < 4; c++) acc[a][b][c] = 0.f;

    const int r8   = lane & 7;
    const int subm = lane >> 3;

    auto load_chunk = [&](int ch, int s) {
        const int kt = ch * 32;
        const uint32_t sbase = sb + s * STG;
#pragma unroll
        for (int i = 0; i < 2; i++) {
            int idx = tid + i * 256;            // 0..511
            int row = idx >> 2;                 // 0..127
            int c   = idx & 3;                  // 16B chunk along k
            uint32_t off = (uint32_t)(row * 64 + ((c ^ ((row >> 1) & 3)) * 16));
            int gr = m0 + row;
            int szA = (gr < NN) ? 16 : 0;
            const __half* pa;
            if (MODE == 0) {
                pa = (kt < 128) ? (g_a1 + (size_t)gr * 128 + kt + c * 8)
                                : (g_xh + (size_t)gr * 128 + (kt - 128) + c * 8);
                if (gr >= NN) pa = g_a1;
            } else {
                pa = g_h + (size_t)gr * 256 + kt + c * 8;
                if (gr >= NN) pa = g_h;
            }
            cpasync16(sbase + OP_A + off, pa, szA);
            cpasync16(sbase + OP_B + off, Bw + (size_t)(j0 + row) * 256 + kt + c * 8, 16);
        }
    };

    load_chunk(0, 0);
    cp_commit();

    for (int ch = 0; ch < 8; ch++) {
        if (ch < 7) load_chunk(ch + 1, (ch + 1) & 1);
        cp_commit();                  // (empty group on last iter)
        cp_wait1();
        __syncthreads();

        const uint32_t sbase = sb + (ch & 1) * STG;
#pragma unroll
        for (int ks = 0; ks < 2; ks++) {
            const int cb = ks * 2;
            uint32_t af[2][4];
#pragma unroll
            for (int tm = 0; tm < 2; tm++) {
                int arow = wm * 32 + tm * 16 + (subm & 1) * 8 + r8;
                int achk = cb + (subm >> 1);
                uint32_t ab = (uint32_t)(arow * 64 + ((achk ^ ((arow >> 1) & 3)) * 16));
                ldsm4(af[tm], sbase + OP_A + ab);
            }
            uint32_t bh[16];
#pragma unroll
            for (int g = 0; g < 4; g++) {
                int brow = wn * 64 + g * 16 + (subm >> 1) * 8 + r8;
                int bchk = cb + (subm & 1);
                uint32_t bb = (uint32_t)(brow * 64 + ((bchk ^ ((brow >> 1) & 3)) * 16));
                ldsm4(&bh[g * 4], sbase + OP_B + bb);
            }
#pragma unroll
            for (int tm = 0; tm < 2; tm++)
#pragma unroll
                for (int tn = 0; tn < 8; tn++)
                    mma_f16(acc[tm][tn], af[tm], bh[tn * 2], bh[tn * 2 + 1]);
        }
        __syncthreads();
    }

    // ---- epilogue --------------------------------------------------------------
    const int qrow = lane >> 2;
    const int qcol = (lane & 3) * 2;
#pragma unroll
    for (int tm = 0; tm < 2; tm++) {
#pragma unroll
        for (int half = 0; half < 2; half++) {
            int gr = m0 + wm * 32 + tm * 16 + half * 8 + qrow;
            if (gr >= NN) continue;
#pragma unroll
            for (int tn = 0; tn < 8; tn++) {
                int gc = j0 + wn * 64 + tn * 8 + qcol;
                float v0 = acc[tm][tn][half * 2 + 0];
                float v1 = acc[tm][tn][half * 2 + 1];
                if (MODE == 0) {
                    v0 = fmaxf(v0 + bias[gc], 0.f);
                    v1 = fmaxf(v1 + bias[gc + 1], 0.f);
                    __half2 hv = __floats2half2_rn(v0, v1);
                    *(__half2*)(g_h + gr * 256 + gc) = hv;
                } else {
                    if (gc < 64) {
                        __half2 hv = __floats2half2_rn(v0, v1);
                        *(__half2*)(g_ph + gr * 64 + gc) = hv;
                    } else {
                        *(float2*)(g_q + gr * 64 + (gc - 64)) = make_float2(v0, v1);
                    }
                }
            }
        }
    }
}

// ---------------- layer-2 segmented mean + epilogue: warp per node ------------
__global__ void k_reduce2(const float* __restrict__ b2, float* __restrict__ out) {
    int wgl = (blockIdx.x * blockDim.x + threadIdx.x) >> 5;
    int lane = threadIdx.x & 31;
    if (wgl >= NN) return;
    int beg = g_off[wgl], end = g_off[wgl + 1];
    float2 acc = make_float2(0.f, 0.f);
    for (int base = beg; base < end; base += 32) {
        int rem = end - base;
        int eid = (lane < rem) ? g_eidx[base + lane] : 0;
        int cnt = rem < 32 ? rem : 32;
#pragma unroll 4
        for (int j = 0; j < cnt; j++) {
            int s = __shfl_sync(0xffffffff, eid, j);
            __half2 hv = ((const __half2*)g_ph)[s * 32 + lane];
            float2 f = __half22float2(hv);
            acc.x += f.x; acc.y += f.y;
        }
    }
    float inv = g_inv[wgl];
    float2 q  = ((const float2*)g_q)[wgl * 32 + lane];
    float2 bb = ((const float2*)b2)[lane];
    float2 r;
    r.x = fmaf(acc.x, inv, bb.x) + q.x;
    r.y = fmaf(acc.y, inv, bb.y) + q.y;
    ((float2*)out)[wgl * 32 + lane] = r;
}

// ---------------- launch ------------------------------------------------------
extern "C" void kernel_launch(void* const* d_in, const int* in_sizes, int n_in,
                              void* d_out, int out_size) {
    const float* x   = (const float*)d_in[0];
    const void*  ei  = d_in[1];
    const float* W1l = (const float*)d_in[2];
    const float* b1  = (const float*)d_in[3];
    const float* W1r = (const float*)d_in[4];
    const float* W2l = (const float*)d_in[5];
    const float* b2  = (const float*)d_in[6];
    const float* W2r = (const float*)d_in[7];
    float* out = (float*)d_out;

    const int SMEM = 2 * STG;   // 32768
    cudaFuncSetAttribute(k_gemm_mma<0>,
                         cudaFuncAttributeMaxDynamicSharedMemorySize, SMEM);
    cudaFuncSetAttribute(k_gemm_mma<1>,
                         cudaFuncAttributeMaxDynamicSharedMemorySize, SMEM);

    k_detect<<<1, 256>>>(ei);
    k_zero_cnt<<<(NN + 255) / 256, 256>>>();
    k_convert<<<(2 * EE + 255) / 256, 256>>>(ei);

    const int PREP_TOT = PREP_X + PREP_W1 + PREP_W2;
    k_prep<<<(PREP_TOT + 255) / 256, 256>>>(x, W1l, W1r, W2l, W2r);

    k_s1<<<NB_SCAN, 512>>>();
    k_s2<<<1, 32>>>();
    k_s3<<<NB_SCAN, 512>>>();
    k_build<<<(EE + 255) / 256, 256>>>();

    k_reduce1<<<(NN * 32 + 255) / 256, 256>>>();

    const int MT = (NN + 127) / 128;   // 782
    k_gemm_mma<0><<<dim3(MT, 2), 256, SMEM>>>(b1);
    k_gemm_mma<1><<<dim3(MT, 1), 256, SMEM>>>(b1);

    k_reduce2<<<(NN * 32 + 255) / 256, 256>>>(b2, out);
}

// round 15
// speedup vs baseline: 1.5843x; 1.0220x over previous
#include <cuda_runtime.h>
#include <cuda_fp16.h>
#include <cstdint>

#define NN   100000
#define EE   1600000
#define IND  128
#define HIDD 256
#define OUTD 64
#define NB_SCAN 196   // ceil(NN/512)

// ---------------- scratch (device globals: allocation-free rule) -------------
__device__ int      g_dst[EE];
__device__ uint16_t g_rank[EE];          // rank of edge within its dst bucket
__device__ int      g_eidx[EE];
__device__ int      g_count[NN];
__device__ int      g_bsum[NB_SCAN];
__device__ int      g_off[NN + 1];
__device__ float    g_inv[NN];
__device__ int      g_is64;

// fp16 operands (single-term: fp32 accumulate, fp16 inputs)
__device__ __align__(16) __half g_xh[NN * 128];    // x fp16
__device__ __align__(16) __half g_a1[NN * 128];    // mean fp16
__device__ __align__(16) __half g_h[NN * 256];     // h fp16
__device__ __align__(16) __half g_w1[256 * 256];
__device__ __align__(16) __half g_w2[128 * 256];
__device__ __align__(16) __half g_ph[NN * 64];     // p fp16
__device__ __align__(16) float  g_q[NN * 64];      // q fp32

// ---------------- helpers -----------------------------------------------------
__device__ __forceinline__ uint32_t smem_u32(const void* p) {
    uint32_t a;
    asm("{ .reg .u64 t; cvta.to.shared.u64 t, %1; cvt.u32.u64 %0, t; }"
        : "=r"(a) : "l"(p));
    return a;
}
__device__ __forceinline__ void ldsm4(uint32_t* r, uint32_t addr) {
    asm volatile("ldmatrix.sync.aligned.m8n8.x4.shared.b16 {%0,%1,%2,%3}, [%4];"
                 : "=r"(r[0]), "=r"(r[1]), "=r"(r[2]), "=r"(r[3]) : "r"(addr));
}
__device__ __forceinline__ void mma_f16(float* d, const uint32_t* a,
                                        uint32_t b0, uint32_t b1) {
    asm volatile(
        "mma.sync.aligned.m16n8k16.row.col.f32.f16.f16.f32 "
        "{%0,%1,%2,%3}, {%4,%5,%6,%7}, {%8,%9}, {%0,%1,%2,%3};"
        : "+f"(d[0]), "+f"(d[1]), "+f"(d[2]), "+f"(d[3])
        : "r"(a[0]), "r"(a[1]), "r"(a[2]), "r"(a[3]), "r"(b0), "r"(b1));
}
__device__ __forceinline__ void cpasync16(uint32_t dst, const void* src, int srcsz) {
    asm volatile("cp.async.cg.shared.global [%0], [%1], 16, %2;"
                 :: "r"(dst), "l"(src), "r"(srcsz));
}
__device__ __forceinline__ void cp_commit() {
    asm volatile("cp.async.commit_group;");
}
__device__ __forceinline__ void cp_wait1() {
    asm volatile("cp.async.wait_group 1;");
}

// ---------------- detect dtype (block 0) + zero counters (all blocks) ----------
__global__ void k_detzero(const void* __restrict__ ei) {
    int t = blockIdx.x * blockDim.x + threadIdx.x;
    if (t < NN) g_count[t] = 0;
    if (blockIdx.x == 0) {
        __shared__ int s_any;
        if (threadIdx.x == 0) s_any = 0;
        __syncthreads();
        const uint2* p = (const uint2*)ei;
        unsigned any = 0;
        for (int i = threadIdx.x; i < 2048; i += blockDim.x) any |= p[i].y;
        if (any) atomicOr(&s_any, 1);
        __syncthreads();
        if (threadIdx.x == 0) g_is64 = (s_any == 0) ? 1 : 0;
    }
}

// dst convert + histogram; atomic return value = rank within dst bucket
__global__ void k_convert(const void* __restrict__ ei) {
    int t = blockIdx.x * blockDim.x + threadIdx.x;
    if (t >= EE) return;
    int v;
    if (g_is64) v = (int)((const long long*)ei)[EE + t];
    else        v = ((const int*)ei)[EE + t];
    g_dst[t] = v;
    g_rank[t] = (uint16_t)atomicAdd(&g_count[v], 1);
}

// ---------------- x -> fp16 AND weight -> fp16 (fused, runs once) --------------
#define PREP_X  (NN * 32)                       // uint2 elements of x
#define PREP_W1 (256 * 256 / 8)                 // 8 halfs per thread
#define PREP_W2 (128 * 256 / 8)
__global__ void k_prep(const float* __restrict__ x,
                       const float* __restrict__ W1l, const float* __restrict__ W1r,
                       const float* __restrict__ W2l, const float* __restrict__ W2r) {
    int t = blockIdx.x * blockDim.x + threadIdx.x;
    if (t < PREP_X) {
        float4 v = ((const float4*)x)[t];
        __half2 a = __floats2half2_rn(v.x, v.y);
        __half2 b = __floats2half2_rn(v.z, v.w);
        uint2 o; o.x = *(uint32_t*)&a; o.y = *(uint32_t*)&b;
        ((uint2*)g_xh)[t] = o;
    } else if (t < PREP_X + PREP_W1) {
        int u = (t - PREP_X) * 8;               // base half index in g_w1
        int row = u >> 8, k = u & 255;
#pragma unroll
        for (int j = 0; j < 8; j++) {
            int kk = k + j;
            float v = (kk < 128) ? W1l[row * 128 + kk] : W1r[row * 128 + (kk - 128)];
            g_w1[u + j] = __float2half_rn(v);
        }
    } else if (t < PREP_X + PREP_W1 + PREP_W2) {
        int u = (t - PREP_X - PREP_W1) * 8;
        int row = u >> 8, k = u & 255;
#pragma unroll
        for (int j = 0; j < 8; j++) {
            float v = (row < 64) ? W2l[row * 256 + k + j] : W2r[(row - 64) * 256 + k + j];
            g_w2[u + j] = __float2half_rn(v);
        }
    }
}

// ---------------- exclusive scan of g_count -> g_off --------------------------
__global__ void k_s1() {
    int t = blockIdx.x * 512 + threadIdx.x;
    int v = (t < NN) ? g_count[t] : 0;
    __shared__ int sw[16];
    int wid = threadIdx.x >> 5, lid = threadIdx.x & 31;
    int s = v;
#pragma unroll
    for (int o = 16; o > 0; o >>= 1) s += __shfl_down_sync(0xffffffff, s, o);
    if (lid == 0) sw[wid] = s;
    __syncthreads();
    if (wid == 0) {
        int x = (lid < 16) ? sw[lid] : 0;
#pragma unroll
        for (int o = 16; o > 0; o >>= 1) x += __shfl_down_sync(0xffffffff, x, o);
        if (lid == 0) g_bsum[blockIdx.x] = x;
    }
}
__global__ void k_s2() {
    if (threadIdx.x == 0) {
        int run = 0;
        for (int i = 0; i < NB_SCAN; i++) { int v = g_bsum[i]; g_bsum[i] = run; run += v; }
        g_off[NN] = run;
    }
}
__global__ void k_s3() {
    __shared__ int sm[512];
    int t = blockIdx.x * 512 + threadIdx.x;
    int v = (t < NN) ? g_count[t] : 0;
    sm[threadIdx.x] = v;
    __syncthreads();
#pragma unroll
    for (int o = 1; o < 512; o <<= 1) {
        int tmp = (threadIdx.x >= o) ? sm[threadIdx.x - o] : 0;
        __syncthreads();
        sm[threadIdx.x] += tmp;
        __syncthreads();
    }
    if (t < NN) g_off[t] = sm[threadIdx.x] - v + g_bsum[blockIdx.x];
}

// ---------------- CSR build: atomic-free; src read straight from edge_index ----
__global__ void k_build(const void* __restrict__ ei) {
    int t = blockIdx.x * blockDim.x + threadIdx.x;
    if (t >= EE) return;
    int s;
    if (g_is64) s = (int)((const long long*)ei)[t];
    else        s = ((const int*)ei)[t];
    int d = g_dst[t];
    g_eidx[g_off[d] + (int)g_rank[t]] = s;
}

// ---------------- layer-1 segmented mean: warp per node ------------------------
__global__ void k_reduce1() {
    int wgl = (blockIdx.x * blockDim.x + threadIdx.x) >> 5;
    int lane = threadIdx.x & 31;
    if (wgl >= NN) return;
    int beg = g_off[wgl], end = g_off[wgl + 1];
    float4 acc = make_float4(0.f, 0.f, 0.f, 0.f);
    for (int base = beg; base < end; base += 32) {
        int rem = end - base;
        int eid = (lane < rem) ? g_eidx[base + lane] : 0;
        int cnt = rem < 32 ? rem : 32;
#pragma unroll 4
        for (int j = 0; j < cnt; j++) {
            int s = __shfl_sync(0xffffffff, eid, j);
            uint2 u = ((const uint2*)g_xh)[s * 32 + lane];
            float2 f0 = __half22float2(*(__half2*)&u.x);
            float2 f1 = __half22float2(*(__half2*)&u.y);
            acc.x += f0.x; acc.y += f0.y; acc.z += f1.x; acc.w += f1.y;
        }
    }
    float inv = 1.0f / fmaxf((float)(end - beg), 1.0f);
    if (lane == 0) g_inv[wgl] = inv;
    __half2 a = __floats2half2_rn(acc.x * inv, acc.y * inv);
    __half2 b = __floats2half2_rn(acc.z * inv, acc.w * inv);
    uint2 o; o.x = *(uint32_t*)&a; o.y = *(uint32_t*)&b;
    ((uint2*)g_a1)[wgl * 32 + lane] = o;
}

// ======================= pipelined single-term fp16 mma.sync GEMM ============
// MODE 0: h = relu([mean|x] @ W1^T + b1)   N=256 (grid.y=2)
// MODE 1: p(fp16)|q(fp32) = H @ W2^T       N=128 (grid.y=1)
#define STG   16384
#define OP_A  0
#define OP_B  8192

template <int MODE>
__global__ __launch_bounds__(256) void k_gemm_mma(const float* __restrict__ bias)
{
    extern __shared__ char smem[];
    const uint32_t sb = smem_u32(smem);

    const int tid  = threadIdx.x;
    const int wid  = tid >> 5;
    const int lane = tid & 31;
    const int wm   = wid & 3;
    const int wn   = wid >> 2;
    const int m0   = blockIdx.x * 128;
    const int j0   = blockIdx.y * 128;

    const __half* Bw = (MODE == 0) ? g_w1 : g_w2;

    float acc[2][8][4];
#pragma unroll
    for (int a = 0; a < 2; a++)
#pragma unroll
        for (int b = 0; b < 8; b++)
#pragma unroll
            for (int c = 0; c < 4; c++) acc[a][b][c] = 0.f;

    const int r8   = lane & 7;
    const int subm = lane >> 3;

    auto load_chunk = [&](int ch, int s) {
        const int kt = ch * 32;
        const uint32_t sbase = sb + s * STG;
#pragma unroll
        for (int i = 0; i < 2; i++) {
            int idx = tid + i * 256;            // 0..511
            int row = idx >> 2;                 // 0..127
            int c   = idx & 3;                  // 16B chunk along k
            uint32_t off = (uint32_t)(row * 64 + ((c ^ ((row >> 1) & 3)) * 16));
            int gr = m0 + row;
            int szA = (gr < NN) ? 16 : 0;
            const __half* pa;
            if (MODE == 0) {
                pa = (kt < 128) ? (g_a1 + (size_t)gr * 128 + kt + c * 8)
                                : (g_xh + (size_t)gr * 128 + (kt - 128) + c * 8);
                if (gr >= NN) pa = g_a1;
            } else {
                pa = g_h + (size_t)gr * 256 + kt + c * 8;
                if (gr >= NN) pa = g_h;
            }
            cpasync16(sbase + OP_A + off, pa, szA);
            cpasync16(sbase + OP_B + off, Bw + (size_t)(j0 + row) * 256 + kt + c * 8, 16);
        }
    };

    load_chunk(0, 0);
    cp_commit();

    for (int ch = 0; ch < 8; ch++) {
        if (ch < 7) load_chunk(ch + 1, (ch + 1) & 1);
        cp_commit();                  // (empty group on last iter)
        cp_wait1();
        __syncthreads();

        const uint32_t sbase = sb + (ch & 1) * STG;
#pragma unroll
        for (int ks = 0; ks < 2; ks++) {
            const int cb = ks * 2;
            uint32_t af[2][4];
#pragma unroll
            for (int tm = 0; tm < 2; tm++) {
                int arow = wm * 32 + tm * 16 + (subm & 1) * 8 + r8;
                int achk = cb + (subm >> 1);
                uint32_t ab = (uint32_t)(arow * 64 + ((achk ^ ((arow >> 1) & 3)) * 16));
                ldsm4(af[tm], sbase + OP_A + ab);
            }
            uint32_t bh[16];
#pragma unroll
            for (int g = 0; g < 4; g++) {
                int brow = wn * 64 + g * 16 + (subm >> 1) * 8 + r8;
                int bchk = cb + (subm & 1);
                uint32_t bb = (uint32_t)(brow * 64 + ((bchk ^ ((brow >> 1) & 3)) * 16));
                ldsm4(&bh[g * 4], sbase + OP_B + bb);
            }
#pragma unroll
            for (int tm = 0; tm < 2; tm++)
#pragma unroll
                for (int tn = 0; tn < 8; tn++)
                    mma_f16(acc[tm][tn], af[tm], bh[tn * 2], bh[tn * 2 + 1]);
        }
        __syncthreads();
    }

    // ---- epilogue --------------------------------------------------------------
    const int qrow = lane >> 2;
    const int qcol = (lane & 3) * 2;
#pragma unroll
    for (int tm = 0; tm < 2; tm++) {
#pragma unroll
        for (int half = 0; half < 2; half++) {
            int gr = m0 + wm * 32 + tm * 16 + half * 8 + qrow;
            if (gr >= NN) continue;
#pragma unroll
            for (int tn = 0; tn < 8; tn++) {
                int gc = j0 + wn * 64 + tn * 8 + qcol;
                float v0 = acc[tm][tn][half * 2 + 0];
                float v1 = acc[tm][tn][half * 2 + 1];
                if (MODE == 0) {
                    v0 = fmaxf(v0 + bias[gc], 0.f);
                    v1 = fmaxf(v1 + bias[gc + 1], 0.f);
                    __half2 hv = __floats2half2_rn(v0, v1);
                    *(__half2*)(g_h + gr * 256 + gc) = hv;
                } else {
                    if (gc < 64) {
                        __half2 hv = __floats2half2_rn(v0, v1);
                        *(__half2*)(g_ph + gr * 64 + gc) = hv;
                    } else {
                        *(float2*)(g_q + gr * 64 + (gc - 64)) = make_float2(v0, v1);
                    }
                }
            }
        }
    }
}

// ---------------- layer-2 segmented mean + epilogue: warp per node ------------
__global__ void k_reduce2(const float* __restrict__ b2, float* __restrict__ out) {
    int wgl = (blockIdx.x * blockDim.x + threadIdx.x) >> 5;
    int lane = threadIdx.x & 31;
    if (wgl >= NN) return;
    int beg = g_off[wgl], end = g_off[wgl + 1];
    float2 acc = make_float2(0.f, 0.f);
    for (int base = beg; base < end; base += 32) {
        int rem = end - base;
        int eid = (lane < rem) ? g_eidx[base + lane] : 0;
        int cnt = rem < 32 ? rem : 32;
#pragma unroll 4
        for (int j = 0; j < cnt; j++) {
            int s = __shfl_sync(0xffffffff, eid, j);
            __half2 hv = ((const __half2*)g_ph)[s * 32 + lane];
            float2 f = __half22float2(hv);
            acc.x += f.x; acc.y += f.y;
        }
    }
    float inv = g_inv[wgl];
    float2 q  = ((const float2*)g_q)[wgl * 32 + lane];
    float2 bb = ((const float2*)b2)[lane];
    float2 r;
    r.x = fmaf(acc.x, inv, bb.x) + q.x;
    r.y = fmaf(acc.y, inv, bb.y) + q.y;
    ((float2*)out)[wgl * 32 + lane] = r;
}

// ---------------- launch ------------------------------------------------------
extern "C" void kernel_launch(void* const* d_in, const int* in_sizes, int n_in,
                              void* d_out, int out_size) {
    const float* x   = (const float*)d_in[0];
    const void*  ei  = d_in[1];
    const float* W1l = (const float*)d_in[2];
    const float* b1  = (const float*)d_in[3];
    const float* W1r = (const float*)d_in[4];
    const float* W2l = (const float*)d_in[5];
    const float* b2  = (const float*)d_in[6];
    const float* W2r = (const float*)d_in[7];
    float* out = (float*)d_out;

    const int SMEM = 2 * STG;   // 32768
    cudaFuncSetAttribute(k_gemm_mma<0>,
                         cudaFuncAttributeMaxDynamicSharedMemorySize, SMEM);
    cudaFuncSetAttribute(k_gemm_mma<1>,
                         cudaFuncAttributeMaxDynamicSharedMemorySize, SMEM);

    // second stream + fork/join events (created once, on the uncaptured
    // correctness call; reused under graph capture). Fallback: single stream.
    static cudaStream_t s2 = nullptr;
    static cudaEvent_t evF = nullptr, evJ = nullptr;
    static int tried = 0;
    if (!tried) {
        tried = 1;
        if (cudaStreamCreateWithFlags(&s2, cudaStreamNonBlocking) != cudaSuccess) s2 = nullptr;
        if (s2) {
            if (cudaEventCreateWithFlags(&evF, cudaEventDisableTiming) != cudaSuccess ||
                cudaEventCreateWithFlags(&evJ, cudaEventDisableTiming) != cudaSuccess) {
                s2 = nullptr;
            }
        }
    }

    const int PREP_TOT = PREP_X + PREP_W1 + PREP_W2;

    if (s2) {
        // fork: prep (x/W -> fp16) runs concurrently with the CSR chain
        cudaEventRecord(evF, 0);
        cudaStreamWaitEvent(s2, evF, 0);
        k_prep<<<(PREP_TOT + 255) / 256, 256, 0, s2>>>(x, W1l, W1r, W2l, W2r);
        cudaEventRecord(evJ, s2);
    } else {
        k_prep<<<(PREP_TOT + 255) / 256, 256>>>(x, W1l, W1r, W2l, W2r);
    }

    // CSR chain on the main stream
    k_detzero<<<(NN + 255) / 256, 256>>>(ei);
    k_convert<<<(EE + 255) / 256, 256>>>(ei);
    k_s1<<<NB_SCAN, 512>>>();
    k_s2<<<1, 32>>>();
    k_s3<<<NB_SCAN, 512>>>();
    k_build<<<(EE + 255) / 256, 256>>>(ei);

    if (s2) cudaStreamWaitEvent(0, evJ, 0);   // join: reduce1 needs g_xh

    k_reduce1<<<(NN * 32 + 255) / 256, 256>>>();

    const int MT = (NN + 127) / 128;   // 782
    k_gemm_mma<0><<<dim3(MT, 2), 256, SMEM>>>(b1);
    k_gemm_mma<1><<<dim3(MT, 1), 256, SMEM>>>(b1);

    k_reduce2<<<(NN * 32 + 255) / 256, 256>>>(b2, out);
}